// round 12
// baseline (speedup 1.0000x reference)
#include <cuda_runtime.h>
#include <math_constants.h>

// Problem constants
#define BB    16
#define CC    256
#define HH    32
#define WW    32
#define EE    256
#define NE    8192
#define HW    1024
#define ROWS  16384   // B*H*W
#define KC    2304    // 9*256 im2col K

#define OUT_ELEMS   4194304
#define LOSS_OFF    4194304
#define IDX_OFF     4194305

#define GBLK  512               // gather blocks (ROWS/32)

typedef unsigned long long u64;

// ---------------- device scratch ----------------
__device__ float g_ze[ROWS * EE];      // conv1 out [row][e] (bit-exact)
__device__ float g_zf[ROWS * EE];      // post-LN  [row][e] (bit-exact)
__device__ float g_znorm[ROWS];        // serial sum zf^2
__device__ float g_enorm[NE];          // serial sum e^2
__device__ float g_wp[KC * EE];        // conv1 W permuted: [(khw*256+ci)][o]
__device__ float g_zq[BB * EE * HW];   // straight-through zq, NCHW
__device__ int   g_idx[ROWS];
__device__ float g_lpart[GBLK];
__device__ float g_cv[32 * ROWS];      // argmin candidates: value  [cand][row]
__device__ int   g_ci[32 * ROWS];      // argmin candidates: index  [cand][row]

// ---------------- packed fp32x2 helpers (Blackwell FFMA2; per-lane IEEE RN) ----------------
__device__ __forceinline__ u64 pack2(float lo, float hi) {
    u64 r;
    asm("mov.b64 %0, {%1, %2};" : "=l"(r)
        : "r"(__float_as_uint(lo)), "r"(__float_as_uint(hi)));
    return r;
}
__device__ __forceinline__ void unpack2(u64 v, float& lo, float& hi) {
    unsigned a, b;
    asm("mov.b64 {%0, %1}, %2;" : "=r"(a), "=r"(b) : "l"(v));
    lo = __uint_as_float(a);
    hi = __uint_as_float(b);
}
__device__ __forceinline__ u64 fma2(u64 a, u64 b, u64 c) {
    u64 d;
    asm("fma.rn.f32x2 %0, %1, %2, %3;" : "=l"(d) : "l"(a), "l"(b), "l"(c));
    return d;
}

// ---------------- helpers ----------------
__device__ __forceinline__ float blk_sum(float v, float* sh) {
    int t = threadIdx.x, lane = t & 31, w = t >> 5;
    #pragma unroll
    for (int o = 16; o; o >>= 1) v += __shfl_down_sync(0xffffffffu, v, o);
    if (!lane) sh[w] = v;
    __syncthreads();
    if (w == 0) {
        float x = (lane < 8) ? sh[lane] : 0.f;
        #pragma unroll
        for (int o = 4; o; o >>= 1) x += __shfl_down_sync(0xffffffffu, x, o);
        if (!lane) sh[0] = x;
    }
    __syncthreads();
    float r = sh[0];
    __syncthreads();
    return r;
}

// ---------------- weight permute: [o][ci][kh][kw] -> [(khw*256+ci)][o] ----------------
// Writes the __device__ global directly — device symbols must never be passed
// as kernel arguments from host code (host shadow symbol != device ptr).
__global__ __launch_bounds__(256) void permw_kernel(const float* __restrict__ Wm) {
    int i = blockIdx.x * 256 + threadIdx.x;       // over KC*EE
    if (i < KC * EE) {
        int o = i & 255;
        int kk = i >> 8;          // (khw)*256 + ci
        int ci = kk & 255;
        int khw = kk >> 8;
        g_wp[kk * 256 + o] = Wm[o * KC + ci * 9 + khw];
    }
}

// ---------------- enorm3: static-smem staged, serial ascending per row ----------------
#define LN_STR 260
__global__ __launch_bounds__(256) void enorm3_kernel(const float* __restrict__ cb) {
    __shared__ float ls[32 * LN_STR];              // 33.3 KB static
    int t = threadIdx.x;
    int r0 = blockIdx.x * 32;
    const float4* src = (const float4*)(cb + r0 * 256);
    #pragma unroll
    for (int e = 0; e < 8; e++) {
        int lin = t + (e << 8);                    // 0..2047
        float4 v = src[lin];
        int row = lin >> 6;
        int kq = (lin & 63) << 2;
        *(float4*)&ls[row * LN_STR + kq] = v;
    }
    __syncthreads();
    if (t < 32) {
        const float* x = ls + t * LN_STR;
        float s = 0.f;
        for (int k = 0; k < 256; k++)
            s = __fadd_rn(s, __fmul_rn(x[k], x[k]));
        g_enorm[r0 + t] = s;
    }
}

// ---------------- conv1: bit-exact serial-k im2col GEMM (packed f32x2) ----------------
__global__ __launch_bounds__(256, 2) void conv1_exact(const float* __restrict__ X,
                                                      const float* __restrict__ bias) {
    __shared__ __align__(16) float As[16][132];
    __shared__ __align__(16) float Bs[16][132];

    int t = threadIdx.x;
    int tx = t & 15, ty = t >> 4;
    int row0 = blockIdx.x * 128;
    int n0 = blockIdx.y * 128;

    u64 acc2[8][4];
    #pragma unroll
    for (int i = 0; i < 8; i++)
        #pragma unroll
        for (int jp = 0; jp < 4; jp++) acc2[i][jp] = 0ull;

    for (int k0 = 0; k0 < KC; k0 += 16) {
        #pragma unroll
        for (int e = 0; e < 8; e++) {
            int lin = t + e * 256;
            int m = lin & 127, k = lin >> 7;
            int kk = k0 + k;
            int ci = kk & 255;
            int khw = kk >> 8;
            int kh = khw / 3, kw = khw - kh * 3;
            int row = row0 + m;
            int b = row >> 10;
            int hw = row & 1023;
            int h = (hw >> 5) + kh - 1;
            int w = (hw & 31) + kw - 1;
            float v = 0.f;
            if ((unsigned)h < 32u && (unsigned)w < 32u)
                v = X[((b * 256 + ci) << 10) + (h << 5) + w];
            As[k][m] = v;
            Bs[k][m] = g_wp[(k0 + k) * 256 + n0 + m];
        }
        __syncthreads();
        #pragma unroll
        for (int k = 0; k < 16; k++) {            // k ascending: serial per-lane chains
            u64 bp[4];
            const u64* Bk = (const u64*)&Bs[k][tx * 8];
            #pragma unroll
            for (int jp = 0; jp < 4; jp++) bp[jp] = Bk[jp];
            #pragma unroll
            for (int i = 0; i < 8; i++) {
                float av = As[k][ty * 8 + i];
                u64 ap = pack2(av, av);
                #pragma unroll
                for (int jp = 0; jp < 4; jp++)
                    acc2[i][jp] = fma2(ap, bp[jp], acc2[i][jp]);
            }
        }
        __syncthreads();
    }

    #pragma unroll
    for (int i = 0; i < 8; i++) {
        int row = row0 + ty * 8 + i;
        #pragma unroll
        for (int jp = 0; jp < 4; jp++) {
            float lo, hi;
            unpack2(acc2[i][jp], lo, hi);
            int n = n0 + tx * 8 + 2 * jp;
            g_ze[row * 256 + n]     = __fadd_rn(lo, bias[n]);
            g_ze[row * 256 + n + 1] = __fadd_rn(hi, bias[n + 1]);
        }
    }
}

// ---------------- ln3: static-smem staged, serial-scalar per row ----------------
__global__ __launch_bounds__(256) void ln3_kernel(const float* __restrict__ g,
                                                  const float* __restrict__ be) {
    __shared__ float ls[32 * LN_STR];              // 33.3 KB static
    __shared__ float gg[256], bb[256];
    int t = threadIdx.x;
    int r0 = blockIdx.x * 32;
    gg[t] = g[t];
    bb[t] = be[t];
    const float4* src = (const float4*)(g_ze + r0 * 256);
    #pragma unroll
    for (int e = 0; e < 8; e++) {
        int lin = t + (e << 8);
        float4 v = src[lin];
        int row = lin >> 6;
        int kq = (lin & 63) << 2;
        *(float4*)&ls[row * LN_STR + kq] = v;
    }
    __syncthreads();
    if (t < 32) {
        float* x = ls + t * LN_STR;
        float s = 0.f;
        for (int k = 0; k < 256; k++) s = __fadd_rn(s, x[k]);
        float mu = __fmul_rn(s, 1.f / 256.f);
        float s2 = 0.f;
        for (int k = 0; k < 256; k++) {
            float tq = __fsub_rn(x[k], mu);
            s2 = __fadd_rn(s2, __fmul_rn(tq, tq));
        }
        float var = __fmul_rn(s2, 1.f / 256.f);
        float rs = __fdiv_rn(1.0f, __fsqrt_rn(__fadd_rn(var, 1e-5f)));
        float zn = 0.f;
        for (int k = 0; k < 256; k++) {
            float tq = __fsub_rn(x[k], mu);
            float a = __fmul_rn(tq, rs);
            float v = __fadd_rn(__fmul_rn(a, gg[k]), bb[k]);
            x[k] = v;                                    // in-place
            zn = __fadd_rn(zn, __fmul_rn(v, v));
        }
        g_znorm[r0 + t] = zn;
    }
    __syncthreads();
    float4* dst = (float4*)(g_zf + r0 * 256);
    #pragma unroll
    for (int e = 0; e < 8; e++) {
        int lin = t + (e << 8);
        int row = lin >> 6;
        int kq = (lin & 63) << 2;
        dst[lin] = *(const float4*)&ls[row * LN_STR + kq];
    }
}

// ---------------- dist_v6: 128x128 tiles, split-n, packed f32x2, candidates to global ----------------
// d_n = RN( RN(znorm + enorm_n) - 2*dot_n ), dot = serial ascending fma over k (per lane).
__global__ __launch_bounds__(256, 2) void dist_v6(const float* __restrict__ cb) {
    __shared__ __align__(16) float As[16][132];
    __shared__ __align__(16) float Bs[16][132];
    __shared__ float zns[128];

    int t = threadIdx.x;
    int tx = t & 15, ty = t >> 4;
    int row0 = blockIdx.x * 128;
    int nbase = blockIdx.y * 4096;

    if (t < 128) zns[t] = g_znorm[row0 + t];
    __syncthreads();

    float best[8];
    int bidx[8];
    #pragma unroll
    for (int i = 0; i < 8; i++) { best[i] = CUDART_INF_F; bidx[i] = 0x7fffffff; }

    #pragma unroll 1
    for (int nt = 0; nt < 32; nt++) {
        int n0 = nbase + nt * 128;

        u64 acc2[8][4];
        #pragma unroll
        for (int i = 0; i < 8; i++)
            #pragma unroll
            for (int jp = 0; jp < 4; jp++) acc2[i][jp] = 0ull;

        #pragma unroll 1
        for (int k0 = 0; k0 < 256; k0 += 16) {
            #pragma unroll
            for (int e = 0; e < 8; e++) {
                int lin = t + e * 256;
                int k = lin & 15, m = lin >> 4;
                As[k][m] = g_zf[(row0 + m) * 256 + k0 + k];
            }
            #pragma unroll
            for (int e = 0; e < 8; e++) {
                int lin = t + e * 256;
                int k = lin & 15, n = lin >> 4;
                Bs[k][n] = cb[(n0 + n) * 256 + k0 + k];
            }
            __syncthreads();
            #pragma unroll
            for (int k = 0; k < 16; k++) {           // k ascending: serial per-lane chains
                u64 bp[4];
                const u64* Bk = (const u64*)&Bs[k][tx * 8];
                #pragma unroll
                for (int jp = 0; jp < 4; jp++) bp[jp] = Bk[jp];
                #pragma unroll
                for (int i = 0; i < 8; i++) {
                    float av = As[k][ty * 8 + i];
                    u64 ap = pack2(av, av);
                    #pragma unroll
                    for (int jp = 0; jp < 4; jp++)
                        acc2[i][jp] = fma2(ap, bp[jp], acc2[i][jp]);
                }
            }
            __syncthreads();
        }

        // argmin epilogue: per-i n ascending (jp asc, lo before hi); strict < keeps lowest
        #pragma unroll
        for (int jp = 0; jp < 4; jp++) {
            int n_lo = n0 + tx * 8 + 2 * jp;
            float en_lo = g_enorm[n_lo];
            float en_hi = g_enorm[n_lo + 1];
            #pragma unroll
            for (int i = 0; i < 8; i++) {
                float lo, hi;
                unpack2(acc2[i][jp], lo, hi);
                float S0 = __fadd_rn(zns[ty * 8 + i], en_lo);
                float d0 = __fsub_rn(S0, __fmul_rn(2.0f, lo));
                if (d0 < best[i]) { best[i] = d0; bidx[i] = n_lo; }
                float S1 = __fadd_rn(zns[ty * 8 + i], en_hi);
                float d1 = __fsub_rn(S1, __fmul_rn(2.0f, hi));
                if (d1 < best[i]) { best[i] = d1; bidx[i] = n_lo + 1; }
            }
        }
    }

    // write per-thread candidates: cand id = by*16 + tx, one per (cand,row)
    int c = blockIdx.y * 16 + tx;
    #pragma unroll
    for (int i = 0; i < 8; i++) {
        int row = row0 + ty * 8 + i;
        g_cv[c * ROWS + row] = best[i];
        g_ci[c * ROWS + row] = bidx[i];
    }
}

// ---------------- argmin merge: exact lowest-index-tie reduction over 32 candidates ----------------
__global__ __launch_bounds__(256) void argmin_merge() {
    int row = blockIdx.x * 256 + threadIdx.x;      // 64 blocks x 256
    float bv = g_cv[row];
    int bi = g_ci[row];
    #pragma unroll 4
    for (int c = 1; c < 32; c++) {
        float v = g_cv[c * ROWS + row];
        int i = g_ci[c * ROWS + row];
        if (v < bv || (v == bv && i < bi)) { bv = v; bi = i; }
    }
    g_idx[row] = bi;
}

// ---------------- gather2: coalesced straight-through + loss partials ----------------
__global__ __launch_bounds__(256) void gather2_kernel(const float* __restrict__ cb) {
    __shared__ float sq[256][33];
    __shared__ int sid[32];
    __shared__ float sh[32];
    int t = threadIdx.x;
    int r0 = blockIdx.x * 32;
    if (t < 32) sid[t] = g_idx[r0 + t];
    __syncthreads();
    float local = 0.f;
    #pragma unroll 4
    for (int i = 0; i < 32; i++) {
        float e = cb[sid[i] * 256 + t];
        float z = g_ze[(r0 + i) * 256 + t];
        float d = __fsub_rn(e, z);
        sq[t][i] = __fadd_rn(z, d);              // straight-through bits
        local += d * d;                          // scalar loss: tolerance ok
    }
    __syncthreads();
    int b = r0 >> 10, hw0 = r0 & 1023;
    int w = t >> 5, lane = t & 31;
    #pragma unroll 4
    for (int eb = 0; eb < 32; eb++) {
        int e = eb * 8 + w;
        g_zq[((b * 256 + e) << 10) + hw0 + lane] = sq[e][lane];
    }
    float s = blk_sum(local, sh);
    if (t == 0) g_lpart[blockIdx.x] = s;
}

// ---------------- conv2 (packed f32x2) ----------------
__global__ __launch_bounds__(256, 2) void conv2_gemm(const float* __restrict__ Wm,
                                                     const float* __restrict__ bias,
                                                     float* __restrict__ outNCHW) {
    __shared__ __align__(16) float As[16][132];
    __shared__ __align__(16) float Bs[16][132];
    int t = threadIdx.x;
    int tx = t & 15, ty = t >> 4;
    int row0 = blockIdx.x * 128;
    int n0 = blockIdx.y * 128;

    u64 acc2[8][4];
    #pragma unroll
    for (int i = 0; i < 8; i++)
        #pragma unroll
        for (int jp = 0; jp < 4; jp++) acc2[i][jp] = 0ull;

    for (int k0 = 0; k0 < KC; k0 += 16) {
        #pragma unroll
        for (int e = 0; e < 8; e++) {
            int lin = t + e * 256;
            int m = lin & 127, k = lin >> 7;
            int kk = k0 + k;
            int ci = kk / 9;
            int r9 = kk - ci * 9;
            int kh = r9 / 3, kw = r9 - kh * 3;
            int row = row0 + m;
            int b = row >> 10;
            int hw = row & 1023;
            int h = (hw >> 5) + kh - 1;
            int w = (hw & 31) + kw - 1;
            float v = 0.f;
            if ((unsigned)h < 32u && (unsigned)w < 32u)
                v = g_zq[((b * 256 + ci) << 10) + (h << 5) + w];
            As[k][m] = v;
        }
        #pragma unroll
        for (int e = 0; e < 8; e++) {
            int lin = t + e * 256;
            int k = lin & 15, n = lin >> 4;
            Bs[k][n] = Wm[(n0 + n) * KC + k0 + k];
        }
        __syncthreads();
        #pragma unroll
        for (int k = 0; k < 16; k++) {
            u64 bp[4];
            const u64* Bk = (const u64*)&Bs[k][tx * 8];
            #pragma unroll
            for (int jp = 0; jp < 4; jp++) bp[jp] = Bk[jp];
            #pragma unroll
            for (int i = 0; i < 8; i++) {
                float av = As[k][ty * 8 + i];
                u64 ap = pack2(av, av);
                #pragma unroll
                for (int jp = 0; jp < 4; jp++)
                    acc2[i][jp] = fma2(ap, bp[jp], acc2[i][jp]);
            }
        }
        __syncthreads();
    }

    #pragma unroll
    for (int i = 0; i < 8; i++) {
        int row = row0 + ty * 8 + i;
        int b = row >> 10;
        int hw = row & 1023;
        #pragma unroll
        for (int jp = 0; jp < 4; jp++) {
            float lo, hi;
            unpack2(acc2[i][jp], lo, hi);
            int n = n0 + tx * 8 + 2 * jp;
            outNCHW[((b * 256 + n) << 10) + hw]       = __fadd_rn(lo, bias[n]);
            outNCHW[((b * 256 + n + 1) << 10) + hw]   = __fadd_rn(hi, bias[n + 1]);
        }
    }
}

// ---------------- finalize: loss + idx ----------------
__global__ __launch_bounds__(256) void finalize_kernel(float* __restrict__ out, int out_size) {
    __shared__ float sh[32];
    int gidx = blockIdx.x * blockDim.x + threadIdx.x;
    if (gidx < ROWS && IDX_OFF + gidx < out_size)
        out[IDX_OFF + gidx] = (float)g_idx[gidx];
    if (blockIdx.x == 0) {
        float s = 0.f;
        for (int k = threadIdx.x; k < GBLK; k += 256) s += g_lpart[k];
        float tot = blk_sum(s, sh);
        if (threadIdx.x == 0 && LOSS_OFF < out_size)
            out[LOSS_OFF] = 1.25f * tot / (float)OUT_ELEMS;
    }
}

// ---------------- launcher ----------------
extern "C" void kernel_launch(void* const* d_in, const int* in_sizes, int n_in,
                              void* d_out, int out_size) {
    (void)in_sizes; (void)n_in;
    const float* z       = (const float*)d_in[0];
    const float* emb_w   = (const float*)d_in[1];
    const float* emb_b   = (const float*)d_in[2];
    const float* ln_g    = (const float*)d_in[3];
    const float* ln_b    = (const float*)d_in[4];
    const float* cb      = (const float*)d_in[5];
    const float* unemb_w = (const float*)d_in[6];
    const float* unemb_b = (const float*)d_in[7];
    float* out = (float*)d_out;

    permw_kernel<<<(KC * EE + 255) / 256, 256>>>(emb_w);
    enorm3_kernel<<<NE / 32, 256>>>(cb);
    conv1_exact<<<dim3(ROWS / 128, 2), 256>>>(z, emb_b);                  // -> g_ze
    ln3_kernel<<<ROWS / 32, 256>>>(ln_g, ln_b);                           // -> g_zf, g_znorm
    dist_v6<<<dim3(ROWS / 128, 2), 256>>>(cb);                            // -> g_cv/g_ci
    argmin_merge<<<ROWS / 256, 256>>>();                                  // -> g_idx
    gather2_kernel<<<GBLK, 256>>>(cb);                                    // -> g_zq, g_lpart
    conv2_gemm<<<dim3(ROWS / 128, 2), 256>>>(unemb_w, unemb_b, out);      // -> out
    finalize_kernel<<<ROWS / 256, 256>>>(out, out_size);
}

// round 13
// speedup vs baseline: 1.2751x; 1.2751x over previous
#include <cuda_runtime.h>
#include <cuda_fp16.h>
#include <math_constants.h>
#include <mma.h>

using namespace nvcuda;

// Problem constants
#define BB    16
#define CC    256
#define HH    32
#define WW    32
#define EE    256
#define NE    8192
#define HW    1024
#define ROWS  16384   // B*H*W
#define KC    2304    // 9*256 im2col K

#define OUT_ELEMS   4194304
#define LOSS_OFF    4194304
#define IDX_OFF     4194305

#define GBLK  512               // gather blocks (ROWS/32)

// ---------------- device scratch ----------------
__device__ float g_ze[ROWS * EE];      // conv1 out [row][e] (bit-exact)
__device__ float g_zf[ROWS * EE];      // post-LN  [row][e] (bit-exact)
__device__ float g_znorm[ROWS];        // serial sum zf^2
__device__ float g_enorm[NE];          // serial sum e^2
__device__ float g_wp[KC * EE];        // conv1 W permuted: [(khw*256+ci)][o]
__device__ float g_zq[BB * EE * HW];   // straight-through zq, NCHW
__device__ int   g_idx[ROWS];
__device__ float g_lpart[GBLK];
__device__ __half g_dot[(size_t)ROWS * NE];  // approx dot (268 MB)

// ---------------- helpers ----------------
__device__ __forceinline__ float blk_sum(float v, float* sh) {
    int t = threadIdx.x, lane = t & 31, w = t >> 5;
    #pragma unroll
    for (int o = 16; o; o >>= 1) v += __shfl_down_sync(0xffffffffu, v, o);
    if (!lane) sh[w] = v;
    __syncthreads();
    if (w == 0) {
        float x = (lane < 8) ? sh[lane] : 0.f;
        #pragma unroll
        for (int o = 4; o; o >>= 1) x += __shfl_down_sync(0xffffffffu, x, o);
        if (!lane) sh[0] = x;
    }
    __syncthreads();
    float r = sh[0];
    __syncthreads();
    return r;
}

// ---------------- weight permute: [o][ci][kh][kw] -> [(khw*256+ci)][o] ----------------
__global__ __launch_bounds__(256) void permw_kernel(const float* __restrict__ Wm) {
    int i = blockIdx.x * 256 + threadIdx.x;
    if (i < KC * EE) {
        int o = i & 255;
        int kk = i >> 8;
        int ci = kk & 255;
        int khw = kk >> 8;
        g_wp[kk * 256 + o] = Wm[o * KC + ci * 9 + khw];
    }
}

// ---------------- enorm3: static-smem staged, serial ascending per row ----------------
#define LN_STR 260
__global__ __launch_bounds__(256) void enorm3_kernel(const float* __restrict__ cb) {
    __shared__ float ls[32 * LN_STR];
    int t = threadIdx.x;
    int r0 = blockIdx.x * 32;
    const float4* src = (const float4*)(cb + r0 * 256);
    #pragma unroll
    for (int e = 0; e < 8; e++) {
        int lin = t + (e << 8);
        float4 v = src[lin];
        int row = lin >> 6;
        int kq = (lin & 63) << 2;
        *(float4*)&ls[row * LN_STR + kq] = v;
    }
    __syncthreads();
    if (t < 32) {
        const float* x = ls + t * LN_STR;
        float s = 0.f;
        for (int k = 0; k < 256; k++)
            s = __fadd_rn(s, __fmul_rn(x[k], x[k]));
        g_enorm[r0 + t] = s;
    }
}

// ---------------- conv1: bit-exact serial-k im2col GEMM (R10-proven) ----------------
__global__ __launch_bounds__(256, 2) void conv1_exact(const float* __restrict__ X,
                                                      const float* __restrict__ bias) {
    __shared__ float As[16][132];
    __shared__ float Bs[16][132];

    int t = threadIdx.x;
    int tx = t & 15, ty = t >> 4;
    int row0 = blockIdx.x * 128;
    int n0 = blockIdx.y * 128;

    float acc[8][8];
    #pragma unroll
    for (int i = 0; i < 8; i++)
        #pragma unroll
        for (int j = 0; j < 8; j++) acc[i][j] = 0.f;

    for (int k0 = 0; k0 < KC; k0 += 16) {
        #pragma unroll
        for (int e = 0; e < 8; e++) {
            int lin = t + e * 256;
            int m = lin & 127, k = lin >> 7;
            int kk = k0 + k;
            int ci = kk & 255;
            int khw = kk >> 8;
            int kh = khw / 3, kw = khw - kh * 3;
            int row = row0 + m;
            int b = row >> 10;
            int hw = row & 1023;
            int h = (hw >> 5) + kh - 1;
            int w = (hw & 31) + kw - 1;
            float v = 0.f;
            if ((unsigned)h < 32u && (unsigned)w < 32u)
                v = X[((b * 256 + ci) << 10) + (h << 5) + w];
            As[k][m] = v;
            Bs[k][m] = g_wp[(k0 + k) * 256 + n0 + m];
        }
        __syncthreads();
        #pragma unroll
        for (int k = 0; k < 16; k++) {
            float a[8], b2[8];
            #pragma unroll
            for (int i = 0; i < 8; i++) a[i] = As[k][ty * 8 + i];
            #pragma unroll
            for (int j = 0; j < 8; j++) b2[j] = Bs[k][tx * 8 + j];
            #pragma unroll
            for (int i = 0; i < 8; i++)
                #pragma unroll
                for (int j = 0; j < 8; j++)
                    acc[i][j] = __fmaf_rn(a[i], b2[j], acc[i][j]);
        }
        __syncthreads();
    }

    #pragma unroll
    for (int i = 0; i < 8; i++) {
        int row = row0 + ty * 8 + i;
        #pragma unroll
        for (int j = 0; j < 8; j++) {
            int n = n0 + tx * 8 + j;
            g_ze[row * 256 + n] = __fadd_rn(acc[i][j], bias[n]);
        }
    }
}

// ---------------- ln3: static-smem staged, serial-scalar per row ----------------
__global__ __launch_bounds__(256) void ln3_kernel(const float* __restrict__ g,
                                                  const float* __restrict__ be) {
    __shared__ float ls[32 * LN_STR];
    __shared__ float gg[256], bb[256];
    int t = threadIdx.x;
    int r0 = blockIdx.x * 32;
    gg[t] = g[t];
    bb[t] = be[t];
    const float4* src = (const float4*)(g_ze + r0 * 256);
    #pragma unroll
    for (int e = 0; e < 8; e++) {
        int lin = t + (e << 8);
        float4 v = src[lin];
        int row = lin >> 6;
        int kq = (lin & 63) << 2;
        *(float4*)&ls[row * LN_STR + kq] = v;
    }
    __syncthreads();
    if (t < 32) {
        float* x = ls + t * LN_STR;
        float s = 0.f;
        for (int k = 0; k < 256; k++) s = __fadd_rn(s, x[k]);
        float mu = __fmul_rn(s, 1.f / 256.f);
        float s2 = 0.f;
        for (int k = 0; k < 256; k++) {
            float tq = __fsub_rn(x[k], mu);
            s2 = __fadd_rn(s2, __fmul_rn(tq, tq));
        }
        float var = __fmul_rn(s2, 1.f / 256.f);
        float rs = __fdiv_rn(1.0f, __fsqrt_rn(__fadd_rn(var, 1e-5f)));
        float zn = 0.f;
        for (int k = 0; k < 256; k++) {
            float tq = __fsub_rn(x[k], mu);
            float a = __fmul_rn(tq, rs);
            float v = __fadd_rn(__fmul_rn(a, gg[k]), bb[k]);
            x[k] = v;
            zn = __fadd_rn(zn, __fmul_rn(v, v));
        }
        g_znorm[r0 + t] = zn;
    }
    __syncthreads();
    float4* dst = (float4*)(g_zf + r0 * 256);
    #pragma unroll
    for (int e = 0; e < 8; e++) {
        int lin = t + (e << 8);
        int row = lin >> 6;
        int kq = (lin & 63) << 2;
        dst[lin] = *(const float4*)&ls[row * LN_STR + kq];
    }
}

// ---------------- distA_wmma: approximate dot via tf32 tensor cores ----------------
// dot_approx[row][n] ~ zf_row . e_n, error bounded by tf32 input rounding.
#define SPAD 40
__global__ __launch_bounds__(256) void distA_wmma(const float* __restrict__ cb) {
    __shared__ float As[128 * SPAD];
    __shared__ float Bs[128 * SPAD];
    int t = threadIdx.x;
    int row0 = blockIdx.x * 128;
    int nc0 = blockIdx.y * 128;
    int wid = t >> 5, lane = t & 31;
    int wm = (wid & 3) * 32;      // warp row offset
    int wn = (wid >> 2) * 64;     // warp col offset

    wmma::fragment<wmma::accumulator, 16, 16, 8, float> acc[2][4];
    #pragma unroll
    for (int i = 0; i < 2; i++)
        #pragma unroll
        for (int j = 0; j < 4; j++) wmma::fill_fragment(acc[i][j], 0.0f);

    for (int k0 = 0; k0 < 256; k0 += 32) {
        #pragma unroll
        for (int e = 0; e < 4; e++) {
            int lin = t + e * 256;          // 0..1023
            int m = lin >> 3;
            int kq = (lin & 7) << 2;
            *(float4*)&As[m * SPAD + kq] = *(const float4*)&g_zf[(row0 + m) * 256 + k0 + kq];
            *(float4*)&Bs[m * SPAD + kq] = *(const float4*)&cb[(nc0 + m) * 256 + k0 + kq];
        }
        __syncthreads();
        #pragma unroll
        for (int ks = 0; ks < 4; ks++) {
            int kk = ks * 8;
            wmma::fragment<wmma::matrix_a, 16, 16, 8, wmma::precision::tf32, wmma::row_major> af[2];
            wmma::fragment<wmma::matrix_b, 16, 16, 8, wmma::precision::tf32, wmma::col_major> bf[4];
            #pragma unroll
            for (int i = 0; i < 2; i++) {
                wmma::load_matrix_sync(af[i], &As[(wm + 16 * i) * SPAD + kk], SPAD);
                #pragma unroll
                for (int x = 0; x < af[i].num_elements; x++)
                    af[i].x[x] = wmma::__float_to_tf32(af[i].x[x]);
            }
            #pragma unroll
            for (int j = 0; j < 4; j++) {
                wmma::load_matrix_sync(bf[j], &Bs[(wn + 16 * j) * SPAD + kk], SPAD);
                #pragma unroll
                for (int x = 0; x < bf[j].num_elements; x++)
                    bf[j].x[x] = wmma::__float_to_tf32(bf[j].x[x]);
            }
            #pragma unroll
            for (int i = 0; i < 2; i++)
                #pragma unroll
                for (int j = 0; j < 4; j++)
                    wmma::mma_sync(acc[i][j], af[i], bf[j], acc[i][j]);
        }
        __syncthreads();
    }

    // epilogue: stage frags through per-warp smem scratch, write fp16 dot
    float* scr = &As[wid * 320];            // 16x20 floats per warp
    #pragma unroll
    for (int i = 0; i < 2; i++)
        #pragma unroll
        for (int j = 0; j < 4; j++) {
            wmma::store_matrix_sync(scr, acc[i][j], 20, wmma::mem_row_major);
            __syncwarp();
            #pragma unroll
            for (int e = 0; e < 8; e++) {
                int idx = lane + e * 32;    // 0..255
                int rr = idx >> 4, cc = idx & 15;
                int grow = row0 + wm + 16 * i + rr;
                int gcol = nc0 + wn + 16 * j + cc;
                g_dot[(size_t)grow * NE + gcol] = __float2half(scr[rr * 20 + cc]);
            }
            __syncwarp();
        }
}

// ---------------- cand_kernel: per-row min + candidate collect + exact rescore ----------------
// Exact chain replayed per candidate: dot = serial ascending fmaf; d = RN(RN(zn+en)-RN(2dot)).
#define CAND_CAP 512
#define MARGIN 3e-4f
__global__ __launch_bounds__(256) void cand_kernel(const float* __restrict__ cb) {
    __shared__ float zfs[4][260];
    __shared__ int   list[4][CAND_CAP];
    __shared__ int   cnt4[4];
    __shared__ float red[8];
    __shared__ float mshared;
    __shared__ unsigned long long bestkey[4];
    __shared__ float cscr[8][264];

    int t = threadIdx.x;
    int r0 = blockIdx.x * 4;
    #pragma unroll
    for (int e = 0; e < 4; e++) {
        int lin = t + e * 256;
        zfs[lin >> 8][lin & 255] = g_zf[(r0 + (lin >> 8)) * 256 + (lin & 255)];
    }
    if (t < 4) { cnt4[t] = 0; bestkey[t] = 0xFFFFFFFFFFFFFFFFull; }
    __syncthreads();

    for (int r = 0; r < 4; r++) {
        size_t rowoff = (size_t)(r0 + r) * NE;
        // pass 1: approx min of v = enorm - 2*dot
        float lm = CUDART_INF_F;
        #pragma unroll 4
        for (int i = 0; i < 32; i++) {
            int n = t + (i << 8);
            float v = g_enorm[n] - 2.f * __half2float(g_dot[rowoff + n]);
            lm = fminf(lm, v);
        }
        #pragma unroll
        for (int o = 16; o; o >>= 1) lm = fminf(lm, __shfl_down_sync(0xffffffffu, lm, o));
        if ((t & 31) == 0) red[t >> 5] = lm;
        __syncthreads();
        if (t == 0) {
            float x = red[0];
            #pragma unroll
            for (int w = 1; w < 8; w++) x = fminf(x, red[w]);
            mshared = x;
        }
        __syncthreads();
        float thr = mshared + MARGIN;
        #pragma unroll 4
        for (int i = 0; i < 32; i++) {
            int n = t + (i << 8);
            float v = g_enorm[n] - 2.f * __half2float(g_dot[rowoff + n]);
            if (v <= thr) {
                int p = atomicAdd(&cnt4[r], 1);
                if (p < CAND_CAP) list[r][p] = n;
            }
        }
        __syncthreads();
    }

    // phase 2: exact rescore — one warp per candidate
    int wid = t >> 5, lane = t & 31;
    for (int r = 0; r < 4; r++) {
        int row = r0 + r;
        int H = min(cnt4[r], CAND_CAP);
        for (int h = wid; h < H; h += 8) {
            int n = list[r][h];
            #pragma unroll
            for (int e = 0; e < 8; e++)
                cscr[wid][lane + e * 32] = cb[n * 256 + lane + e * 32];
            __syncwarp();
            if (lane == 0) {
                float dot = 0.f;
                for (int k = 0; k < 256; k++)
                    dot = __fmaf_rn(zfs[r][k], cscr[wid][k], dot);
                float S = __fadd_rn(g_znorm[row], g_enorm[n]);
                float d = __fsub_rn(S, __fmul_rn(2.0f, dot));
                unsigned long long key =
                    (((unsigned long long)__float_as_uint(d)) << 32) | (unsigned)n;
                atomicMin(&bestkey[r], key);
            }
            __syncwarp();
        }
    }
    __syncthreads();
    if (t < 4) g_idx[r0 + t] = (int)(bestkey[t] & 0xFFFFFFFFull);
}

// ---------------- gather2: coalesced straight-through + loss partials ----------------
__global__ __launch_bounds__(256) void gather2_kernel(const float* __restrict__ cb) {
    __shared__ float sq[256][33];
    __shared__ int sid[32];
    __shared__ float sh[32];
    int t = threadIdx.x;
    int r0 = blockIdx.x * 32;
    if (t < 32) sid[t] = g_idx[r0 + t];
    __syncthreads();
    float local = 0.f;
    #pragma unroll 4
    for (int i = 0; i < 32; i++) {
        float e = cb[sid[i] * 256 + t];
        float z = g_ze[(r0 + i) * 256 + t];
        float d = __fsub_rn(e, z);
        sq[t][i] = __fadd_rn(z, d);              // straight-through bits
        local += d * d;
    }
    __syncthreads();
    int b = r0 >> 10, hw0 = r0 & 1023;
    int w = t >> 5, lane = t & 31;
    #pragma unroll 4
    for (int eb = 0; eb < 32; eb++) {
        int e = eb * 8 + w;
        g_zq[((b * 256 + e) << 10) + hw0 + lane] = sq[e][lane];
    }
    float s = blk_sum(local, sh);
    if (t == 0) g_lpart[blockIdx.x] = s;
}

// ---------------- conv2 (R10-proven) ----------------
__global__ __launch_bounds__(256, 2) void conv2_gemm(const float* __restrict__ Wm,
                                                     const float* __restrict__ bias,
                                                     float* __restrict__ outNCHW) {
    __shared__ float As[16][132];
    __shared__ float Bs[16][132];
    int t = threadIdx.x;
    int tx = t & 15, ty = t >> 4;
    int row0 = blockIdx.x * 128;
    int n0 = blockIdx.y * 128;

    float acc[8][8];
    #pragma unroll
    for (int i = 0; i < 8; i++)
        #pragma unroll
        for (int j = 0; j < 8; j++) acc[i][j] = 0.f;

    for (int k0 = 0; k0 < KC; k0 += 16) {
        #pragma unroll
        for (int e = 0; e < 8; e++) {
            int lin = t + e * 256;
            int m = lin & 127, k = lin >> 7;
            int kk = k0 + k;
            int ci = kk / 9;
            int r9 = kk - ci * 9;
            int kh = r9 / 3, kw = r9 - kh * 3;
            int row = row0 + m;
            int b = row >> 10;
            int hw = row & 1023;
            int h = (hw >> 5) + kh - 1;
            int w = (hw & 31) + kw - 1;
            float v = 0.f;
            if ((unsigned)h < 32u && (unsigned)w < 32u)
                v = g_zq[((b * 256 + ci) << 10) + (h << 5) + w];
            As[k][m] = v;
        }
        #pragma unroll
        for (int e = 0; e < 8; e++) {
            int lin = t + e * 256;
            int k = lin & 15, n = lin >> 4;
            Bs[k][n] = Wm[(n0 + n) * KC + k0 + k];
        }
        __syncthreads();
        #pragma unroll
        for (int k = 0; k < 16; k++) {
            float a[8], b2[8];
            #pragma unroll
            for (int i = 0; i < 8; i++) a[i] = As[k][ty * 8 + i];
            #pragma unroll
            for (int j = 0; j < 8; j++) b2[j] = Bs[k][tx * 8 + j];
            #pragma unroll
            for (int i = 0; i < 8; i++)
                #pragma unroll
                for (int j = 0; j < 8; j++)
                    acc[i][j] = __fmaf_rn(a[i], b2[j], acc[i][j]);
        }
        __syncthreads();
    }

    #pragma unroll
    for (int i = 0; i < 8; i++) {
        int row = row0 + ty * 8 + i;
        int b = row >> 10;
        int hw = row & 1023;
        #pragma unroll
        for (int j = 0; j < 8; j++) {
            int n = n0 + tx * 8 + j;
            outNCHW[((b * 256 + n) << 10) + hw] = __fadd_rn(acc[i][j], bias[n]);
        }
    }
}

// ---------------- finalize: loss + idx ----------------
__global__ __launch_bounds__(256) void finalize_kernel(float* __restrict__ out, int out_size) {
    __shared__ float sh[32];
    int gidx = blockIdx.x * blockDim.x + threadIdx.x;
    if (gidx < ROWS && IDX_OFF + gidx < out_size)
        out[IDX_OFF + gidx] = (float)g_idx[gidx];
    if (blockIdx.x == 0) {
        float s = 0.f;
        for (int k = threadIdx.x; k < GBLK; k += 256) s += g_lpart[k];
        float tot = blk_sum(s, sh);
        if (threadIdx.x == 0 && LOSS_OFF < out_size)
            out[LOSS_OFF] = 1.25f * tot / (float)OUT_ELEMS;
    }
}

// ---------------- launcher ----------------
extern "C" void kernel_launch(void* const* d_in, const int* in_sizes, int n_in,
                              void* d_out, int out_size) {
    (void)in_sizes; (void)n_in;
    const float* z       = (const float*)d_in[0];
    const float* emb_w   = (const float*)d_in[1];
    const float* emb_b   = (const float*)d_in[2];
    const float* ln_g    = (const float*)d_in[3];
    const float* ln_b    = (const float*)d_in[4];
    const float* cb      = (const float*)d_in[5];
    const float* unemb_w = (const float*)d_in[6];
    const float* unemb_b = (const float*)d_in[7];
    float* out = (float*)d_out;

    permw_kernel<<<(KC * EE + 255) / 256, 256>>>(emb_w);
    enorm3_kernel<<<NE / 32, 256>>>(cb);
    conv1_exact<<<dim3(ROWS / 128, 2), 256>>>(z, emb_b);                  // -> g_ze
    ln3_kernel<<<ROWS / 32, 256>>>(ln_g, ln_b);                           // -> g_zf, g_znorm
    distA_wmma<<<dim3(ROWS / 128, NE / 128), 256>>>(cb);                  // -> g_dot (approx)
    cand_kernel<<<ROWS / 4, 256>>>(cb);                                   // -> g_idx (exact)
    gather2_kernel<<<GBLK, 256>>>(cb);                                    // -> g_zq, g_lpart
    conv2_gemm<<<dim3(ROWS / 128, 2), 256>>>(unemb_w, unemb_b, out);      // -> out
    finalize_kernel<<<ROWS / 256, 256>>>(out, out_size);
}

// round 14
// speedup vs baseline: 1.6266x; 1.2757x over previous
#include <cuda_runtime.h>
#include <cuda_fp16.h>
#include <cuda_bf16.h>
#include <math_constants.h>
#include <mma.h>

using namespace nvcuda;

// Problem constants
#define BB    16
#define CC    256
#define HH    32
#define WW    32
#define EE    256
#define NE    8192
#define HW    1024
#define ROWS  16384   // B*H*W
#define KC    2304    // 9*256 im2col K

#define OUT_ELEMS   4194304
#define LOSS_OFF    4194304
#define IDX_OFF     4194305

#define GBLK  512               // gather blocks (ROWS/32)

// ---------------- device scratch ----------------
__device__ float g_ze[ROWS * EE];      // conv1 out [row][e] (bit-exact)
__device__ float g_zf[ROWS * EE];      // post-LN  [row][e] (bit-exact)
__device__ float g_znorm[ROWS];        // serial sum zf^2
__device__ float g_enorm[NE];          // serial sum e^2
__device__ float g_wp[KC * EE];        // conv1 W permuted
__device__ float g_zq[BB * EE * HW];   // straight-through zq, NCHW
__device__ int   g_idx[ROWS];
__device__ float g_lpart[GBLK];
__device__ __align__(16) __nv_bfloat16 g_zfh[ROWS * EE];   // zf in bf16
__device__ __align__(16) __nv_bfloat16 g_cbh[NE * EE];     // codebook in bf16
__device__ __half g_v[(size_t)ROWS * NE];                  // approx v = enorm - 2*dot (fp16)
__device__ unsigned g_rowmin[ROWS];                        // per-row min of v (ordered-uint)

// ---------------- helpers ----------------
__device__ __forceinline__ float blk_sum(float v, float* sh) {
    int t = threadIdx.x, lane = t & 31, w = t >> 5;
    #pragma unroll
    for (int o = 16; o; o >>= 1) v += __shfl_down_sync(0xffffffffu, v, o);
    if (!lane) sh[w] = v;
    __syncthreads();
    if (w == 0) {
        float x = (lane < 8) ? sh[lane] : 0.f;
        #pragma unroll
        for (int o = 4; o; o >>= 1) x += __shfl_down_sync(0xffffffffu, x, o);
        if (!lane) sh[0] = x;
    }
    __syncthreads();
    float r = sh[0];
    __syncthreads();
    return r;
}

__device__ __forceinline__ unsigned fenc(float x) {
    unsigned u = __float_as_uint(x);
    return (u & 0x80000000u) ? ~u : (u | 0x80000000u);
}
__device__ __forceinline__ float fdec(unsigned y) {
    unsigned u = (y & 0x80000000u) ? (y ^ 0x80000000u) : ~y;
    return __uint_as_float(u);
}

// ---------------- weight permute ----------------
__global__ __launch_bounds__(256) void permw_kernel(const float* __restrict__ Wm) {
    int i = blockIdx.x * 256 + threadIdx.x;
    if (i < KC * EE) {
        int o = i & 255;
        int kk = i >> 8;
        int ci = kk & 255;
        int khw = kk >> 8;
        g_wp[kk * 256 + o] = Wm[o * KC + ci * 9 + khw];
    }
}

// ---------------- enorm3 ----------------
#define LN_STR 260
__global__ __launch_bounds__(256) void enorm3_kernel(const float* __restrict__ cb) {
    __shared__ float ls[32 * LN_STR];
    int t = threadIdx.x;
    int r0 = blockIdx.x * 32;
    const float4* src = (const float4*)(cb + r0 * 256);
    #pragma unroll
    for (int e = 0; e < 8; e++) {
        int lin = t + (e << 8);
        float4 v = src[lin];
        int row = lin >> 6;
        int kq = (lin & 63) << 2;
        *(float4*)&ls[row * LN_STR + kq] = v;
    }
    __syncthreads();
    if (t < 32) {
        const float* x = ls + t * LN_STR;
        float s = 0.f;
        for (int k = 0; k < 256; k++)
            s = __fadd_rn(s, __fmul_rn(x[k], x[k]));
        g_enorm[r0 + t] = s;
    }
}

// ---------------- conv1: bit-exact serial-k im2col GEMM ----------------
__global__ __launch_bounds__(256, 2) void conv1_exact(const float* __restrict__ X,
                                                      const float* __restrict__ bias) {
    __shared__ float As[16][132];
    __shared__ float Bs[16][132];

    int t = threadIdx.x;
    int tx = t & 15, ty = t >> 4;
    int row0 = blockIdx.x * 128;
    int n0 = blockIdx.y * 128;

    float acc[8][8];
    #pragma unroll
    for (int i = 0; i < 8; i++)
        #pragma unroll
        for (int j = 0; j < 8; j++) acc[i][j] = 0.f;

    for (int k0 = 0; k0 < KC; k0 += 16) {
        #pragma unroll
        for (int e = 0; e < 8; e++) {
            int lin = t + e * 256;
            int m = lin & 127, k = lin >> 7;
            int kk = k0 + k;
            int ci = kk & 255;
            int khw = kk >> 8;
            int kh = khw / 3, kw = khw - kh * 3;
            int row = row0 + m;
            int b = row >> 10;
            int hw = row & 1023;
            int h = (hw >> 5) + kh - 1;
            int w = (hw & 31) + kw - 1;
            float v = 0.f;
            if ((unsigned)h < 32u && (unsigned)w < 32u)
                v = X[((b * 256 + ci) << 10) + (h << 5) + w];
            As[k][m] = v;
            Bs[k][m] = g_wp[(k0 + k) * 256 + n0 + m];
        }
        __syncthreads();
        #pragma unroll
        for (int k = 0; k < 16; k++) {
            float a[8], b2[8];
            #pragma unroll
            for (int i = 0; i < 8; i++) a[i] = As[k][ty * 8 + i];
            #pragma unroll
            for (int j = 0; j < 8; j++) b2[j] = Bs[k][tx * 8 + j];
            #pragma unroll
            for (int i = 0; i < 8; i++)
                #pragma unroll
                for (int j = 0; j < 8; j++)
                    acc[i][j] = __fmaf_rn(a[i], b2[j], acc[i][j]);
        }
        __syncthreads();
    }

    #pragma unroll
    for (int i = 0; i < 8; i++) {
        int row = row0 + ty * 8 + i;
        #pragma unroll
        for (int j = 0; j < 8; j++) {
            int n = n0 + tx * 8 + j;
            g_ze[row * 256 + n] = __fadd_rn(acc[i][j], bias[n]);
        }
    }
}

// ---------------- ln3 ----------------
__global__ __launch_bounds__(256) void ln3_kernel(const float* __restrict__ g,
                                                  const float* __restrict__ be) {
    __shared__ float ls[32 * LN_STR];
    __shared__ float gg[256], bb[256];
    int t = threadIdx.x;
    int r0 = blockIdx.x * 32;
    gg[t] = g[t];
    bb[t] = be[t];
    const float4* src = (const float4*)(g_ze + r0 * 256);
    #pragma unroll
    for (int e = 0; e < 8; e++) {
        int lin = t + (e << 8);
        float4 v = src[lin];
        int row = lin >> 6;
        int kq = (lin & 63) << 2;
        *(float4*)&ls[row * LN_STR + kq] = v;
    }
    __syncthreads();
    if (t < 32) {
        float* x = ls + t * LN_STR;
        float s = 0.f;
        for (int k = 0; k < 256; k++) s = __fadd_rn(s, x[k]);
        float mu = __fmul_rn(s, 1.f / 256.f);
        float s2 = 0.f;
        for (int k = 0; k < 256; k++) {
            float tq = __fsub_rn(x[k], mu);
            s2 = __fadd_rn(s2, __fmul_rn(tq, tq));
        }
        float var = __fmul_rn(s2, 1.f / 256.f);
        float rs = __fdiv_rn(1.0f, __fsqrt_rn(__fadd_rn(var, 1e-5f)));
        float zn = 0.f;
        for (int k = 0; k < 256; k++) {
            float tq = __fsub_rn(x[k], mu);
            float a = __fmul_rn(tq, rs);
            float v = __fadd_rn(__fmul_rn(a, gg[k]), bb[k]);
            x[k] = v;
            zn = __fadd_rn(zn, __fmul_rn(v, v));
        }
        g_znorm[r0 + t] = zn;
    }
    __syncthreads();
    float4* dst = (float4*)(g_zf + r0 * 256);
    #pragma unroll
    for (int e = 0; e < 8; e++) {
        int lin = t + (e << 8);
        int row = lin >> 6;
        int kq = (lin & 63) << 2;
        dst[lin] = *(const float4*)&ls[row * LN_STR + kq];
    }
}

// ---------------- prep: zf/cb -> bf16, init rowmin ----------------
__global__ __launch_bounds__(256) void prep_bf16(const float* __restrict__ cb) {
    int i = blockIdx.x * 256 + threadIdx.x;   // over (ROWS*EE + NE*EE)/4 = 1572864
    const int ZQ = ROWS * EE / 4;
    if (i < ZQ) {
        float4 v = ((const float4*)g_zf)[i];
        ((__nv_bfloat162*)g_zfh)[2 * i]     = __floats2bfloat162_rn(v.x, v.y);
        ((__nv_bfloat162*)g_zfh)[2 * i + 1] = __floats2bfloat162_rn(v.z, v.w);
    } else if (i < ZQ + NE * EE / 4) {
        int j = i - ZQ;
        float4 v = ((const float4*)cb)[j];
        ((__nv_bfloat162*)g_cbh)[2 * j]     = __floats2bfloat162_rn(v.x, v.y);
        ((__nv_bfloat162*)g_cbh)[2 * j + 1] = __floats2bfloat162_rn(v.z, v.w);
    }
    if (i < ROWS) g_rowmin[i] = 0xFFFFFFFFu;
}

// ---------------- distB_wmma: bf16 tensor-core approx v + fused rowmin ----------------
#define BSP 72
__global__ __launch_bounds__(256) void distB_wmma() {
    __shared__ __nv_bfloat16 As[128 * BSP];   // 18432 B
    __shared__ __nv_bfloat16 Bs[128 * BSP];   // 18432 B
    __shared__ float scr[8][320];             // 10240 B
    __shared__ unsigned sMin[128];

    int t = threadIdx.x;
    int row0 = blockIdx.x * 128;
    int nc0 = blockIdx.y * 128;
    int wid = t >> 5, lane = t & 31;
    int wm = (wid & 3) * 32;
    int wn = (wid >> 2) * 64;

    wmma::fragment<wmma::accumulator, 16, 16, 16, float> acc[2][4];
    #pragma unroll
    for (int i = 0; i < 2; i++)
        #pragma unroll
        for (int j = 0; j < 4; j++) wmma::fill_fragment(acc[i][j], 0.0f);

    for (int k0 = 0; k0 < 256; k0 += 64) {
        #pragma unroll
        for (int e = 0; e < 4; e++) {
            int lin = t + e * 256;            // 0..1023
            int m = lin >> 3;
            int q = (lin & 7) << 3;           // bf16 offset, 8 per uint4
            *(uint4*)&As[m * BSP + q] = *(const uint4*)&g_zfh[(row0 + m) * 256 + k0 + q];
            *(uint4*)&Bs[m * BSP + q] = *(const uint4*)&g_cbh[(nc0 + m) * 256 + k0 + q];
        }
        __syncthreads();
        #pragma unroll
        for (int ks = 0; ks < 4; ks++) {
            int kk = ks * 16;
            wmma::fragment<wmma::matrix_a, 16, 16, 16, __nv_bfloat16, wmma::row_major> af[2];
            wmma::fragment<wmma::matrix_b, 16, 16, 16, __nv_bfloat16, wmma::col_major> bf[4];
            #pragma unroll
            for (int i = 0; i < 2; i++)
                wmma::load_matrix_sync(af[i], &As[(wm + 16 * i) * BSP + kk], BSP);
            #pragma unroll
            for (int j = 0; j < 4; j++)
                wmma::load_matrix_sync(bf[j], &Bs[(wn + 16 * j) * BSP + kk], BSP);
            #pragma unroll
            for (int i = 0; i < 2; i++)
                #pragma unroll
                for (int j = 0; j < 4; j++)
                    wmma::mma_sync(acc[i][j], af[i], bf[j], acc[i][j]);
        }
        __syncthreads();
    }

    if (t < 128) sMin[t] = 0xFFFFFFFFu;
    __syncthreads();

    #pragma unroll
    for (int i = 0; i < 2; i++)
        #pragma unroll
        for (int j = 0; j < 4; j++) {
            wmma::store_matrix_sync(scr[wid], acc[i][j], 20, wmma::mem_row_major);
            __syncwarp();
            #pragma unroll
            for (int e = 0; e < 8; e++) {
                int idx = lane + e * 32;      // 0..255
                int rr = idx >> 4, cc = idx & 15;
                int grow = row0 + wm + 16 * i + rr;
                int gcol = nc0 + wn + 16 * j + cc;
                float v = g_enorm[gcol] - 2.f * scr[wid][rr * 20 + cc];
                g_v[(size_t)grow * NE + gcol] = __float2half(v);
                atomicMin(&sMin[wm + 16 * i + rr], fenc(v));
            }
            __syncwarp();
        }
    __syncthreads();
    if (t < 128) atomicMin(&g_rowmin[row0 + t], sMin[t]);
}

// ---------------- cand2: single-pass collect + exact rescore ----------------
#define CAND_CAP 512
#define MARGIN 1.2e-3f
__global__ __launch_bounds__(256) void cand2_kernel(const float* __restrict__ cb) {
    __shared__ float zfs[4][260];
    __shared__ int   list[4][CAND_CAP];
    __shared__ int   cnt4[4];
    __shared__ unsigned long long bestkey[4];
    __shared__ float cscr[8][264];

    int t = threadIdx.x;
    int r0 = blockIdx.x * 4;
    #pragma unroll
    for (int e = 0; e < 4; e++) {
        int lin = t + e * 256;
        zfs[lin >> 8][lin & 255] = g_zf[(r0 + (lin >> 8)) * 256 + (lin & 255)];
    }
    if (t < 4) { cnt4[t] = 0; bestkey[t] = 0xFFFFFFFFFFFFFFFFull; }
    __syncthreads();

    for (int r = 0; r < 4; r++) {
        size_t rowoff = (size_t)(r0 + r) * NE;
        float thr = fdec(g_rowmin[r0 + r]) + MARGIN;
        #pragma unroll 4
        for (int i = 0; i < 32; i++) {
            int n = t + (i << 8);
            float v = __half2float(g_v[rowoff + n]);
            if (v <= thr) {
                int p = atomicAdd(&cnt4[r], 1);
                if (p < CAND_CAP) list[r][p] = n;
            }
        }
        __syncthreads();
    }

    // exact rescore — one warp per candidate; bit-identical serial chain
    int wid = t >> 5, lane = t & 31;
    for (int r = 0; r < 4; r++) {
        int row = r0 + r;
        int H = min(cnt4[r], CAND_CAP);
        for (int h = wid; h < H; h += 8) {
            int n = list[r][h];
            #pragma unroll
            for (int e = 0; e < 8; e++)
                cscr[wid][lane + e * 32] = cb[n * 256 + lane + e * 32];
            __syncwarp();
            if (lane == 0) {
                float dot = 0.f;
                for (int k = 0; k < 256; k++)
                    dot = __fmaf_rn(zfs[r][k], cscr[wid][k], dot);
                float S = __fadd_rn(g_znorm[row], g_enorm[n]);
                float d = __fsub_rn(S, __fmul_rn(2.0f, dot));
                unsigned long long key =
                    (((unsigned long long)__float_as_uint(d)) << 32) | (unsigned)n;
                atomicMin(&bestkey[r], key);
            }
            __syncwarp();
        }
    }
    __syncthreads();
    if (t < 4) g_idx[r0 + t] = (int)(bestkey[t] & 0xFFFFFFFFull);
}

// ---------------- gather2 ----------------
__global__ __launch_bounds__(256) void gather2_kernel(const float* __restrict__ cb) {
    __shared__ float sq[256][33];
    __shared__ int sid[32];
    __shared__ float sh[32];
    int t = threadIdx.x;
    int r0 = blockIdx.x * 32;
    if (t < 32) sid[t] = g_idx[r0 + t];
    __syncthreads();
    float local = 0.f;
    #pragma unroll 4
    for (int i = 0; i < 32; i++) {
        float e = cb[sid[i] * 256 + t];
        float z = g_ze[(r0 + i) * 256 + t];
        float d = __fsub_rn(e, z);
        sq[t][i] = __fadd_rn(z, d);
        local += d * d;
    }
    __syncthreads();
    int b = r0 >> 10, hw0 = r0 & 1023;
    int w = t >> 5, lane = t & 31;
    #pragma unroll 4
    for (int eb = 0; eb < 32; eb++) {
        int e = eb * 8 + w;
        g_zq[((b * 256 + e) << 10) + hw0 + lane] = sq[e][lane];
    }
    float s = blk_sum(local, sh);
    if (t == 0) g_lpart[blockIdx.x] = s;
}

// ---------------- conv2 ----------------
__global__ __launch_bounds__(256, 2) void conv2_gemm(const float* __restrict__ Wm,
                                                     const float* __restrict__ bias,
                                                     float* __restrict__ outNCHW) {
    __shared__ float As[16][132];
    __shared__ float Bs[16][132];
    int t = threadIdx.x;
    int tx = t & 15, ty = t >> 4;
    int row0 = blockIdx.x * 128;
    int n0 = blockIdx.y * 128;

    float acc[8][8];
    #pragma unroll
    for (int i = 0; i < 8; i++)
        #pragma unroll
        for (int j = 0; j < 8; j++) acc[i][j] = 0.f;

    for (int k0 = 0; k0 < KC; k0 += 16) {
        #pragma unroll
        for (int e = 0; e < 8; e++) {
            int lin = t + e * 256;
            int m = lin & 127, k = lin >> 7;
            int kk = k0 + k;
            int ci = kk / 9;
            int r9 = kk - ci * 9;
            int kh = r9 / 3, kw = r9 - kh * 3;
            int row = row0 + m;
            int b = row >> 10;
            int hw = row & 1023;
            int h = (hw >> 5) + kh - 1;
            int w = (hw & 31) + kw - 1;
            float v = 0.f;
            if ((unsigned)h < 32u && (unsigned)w < 32u)
                v = g_zq[((b * 256 + ci) << 10) + (h << 5) + w];
            As[k][m] = v;
        }
        #pragma unroll
        for (int e = 0; e < 8; e++) {
            int lin = t + e * 256;
            int k = lin & 15, n = lin >> 4;
            Bs[k][n] = Wm[(n0 + n) * KC + k0 + k];
        }
        __syncthreads();
        #pragma unroll
        for (int k = 0; k < 16; k++) {
            float a[8], b2[8];
            #pragma unroll
            for (int i = 0; i < 8; i++) a[i] = As[k][ty * 8 + i];
            #pragma unroll
            for (int j = 0; j < 8; j++) b2[j] = Bs[k][tx * 8 + j];
            #pragma unroll
            for (int i = 0; i < 8; i++)
                #pragma unroll
                for (int j = 0; j < 8; j++)
                    acc[i][j] = __fmaf_rn(a[i], b2[j], acc[i][j]);
        }
        __syncthreads();
    }

    #pragma unroll
    for (int i = 0; i < 8; i++) {
        int row = row0 + ty * 8 + i;
        int b = row >> 10;
        int hw = row & 1023;
        #pragma unroll
        for (int j = 0; j < 8; j++) {
            int n = n0 + tx * 8 + j;
            outNCHW[((b * 256 + n) << 10) + hw] = __fadd_rn(acc[i][j], bias[n]);
        }
    }
}

// ---------------- finalize ----------------
__global__ __launch_bounds__(256) void finalize_kernel(float* __restrict__ out, int out_size) {
    __shared__ float sh[32];
    int gidx = blockIdx.x * blockDim.x + threadIdx.x;
    if (gidx < ROWS && IDX_OFF + gidx < out_size)
        out[IDX_OFF + gidx] = (float)g_idx[gidx];
    if (blockIdx.x == 0) {
        float s = 0.f;
        for (int k = threadIdx.x; k < GBLK; k += 256) s += g_lpart[k];
        float tot = blk_sum(s, sh);
        if (threadIdx.x == 0 && LOSS_OFF < out_size)
            out[LOSS_OFF] = 1.25f * tot / (float)OUT_ELEMS;
    }
}

// ---------------- launcher ----------------
extern "C" void kernel_launch(void* const* d_in, const int* in_sizes, int n_in,
                              void* d_out, int out_size) {
    (void)in_sizes; (void)n_in;
    const float* z       = (const float*)d_in[0];
    const float* emb_w   = (const float*)d_in[1];
    const float* emb_b   = (const float*)d_in[2];
    const float* ln_g    = (const float*)d_in[3];
    const float* ln_b    = (const float*)d_in[4];
    const float* cb      = (const float*)d_in[5];
    const float* unemb_w = (const float*)d_in[6];
    const float* unemb_b = (const float*)d_in[7];
    float* out = (float*)d_out;

    permw_kernel<<<(KC * EE + 255) / 256, 256>>>(emb_w);
    enorm3_kernel<<<NE / 32, 256>>>(cb);
    conv1_exact<<<dim3(ROWS / 128, 2), 256>>>(z, emb_b);                  // -> g_ze
    ln3_kernel<<<ROWS / 32, 256>>>(ln_g, ln_b);                           // -> g_zf, g_znorm
    prep_bf16<<<(ROWS * EE + NE * EE) / 4 / 256, 256>>>(cb);              // -> g_zfh/g_cbh/rowmin
    distB_wmma<<<dim3(ROWS / 128, NE / 128), 256>>>();                    // -> g_v, g_rowmin
    cand2_kernel<<<ROWS / 4, 256>>>(cb);                                  // -> g_idx (exact)
    gather2_kernel<<<GBLK, 256>>>(cb);                                    // -> g_zq, g_lpart
    conv2_gemm<<<dim3(ROWS / 128, 2), 256>>>(unemb_w, unemb_b, out);      // -> out
    finalize_kernel<<<ROWS / 256, 256>>>(out, out_size);
}

// round 15
// speedup vs baseline: 2.0565x; 1.2643x over previous
#include <cuda_runtime.h>
#include <cuda_fp16.h>
#include <cuda_bf16.h>
#include <math_constants.h>
#include <mma.h>

using namespace nvcuda;

// Problem constants
#define BB    16
#define CC    256
#define HH    32
#define WW    32
#define EE    256
#define NE    8192
#define HW    1024
#define ROWS  16384   // B*H*W
#define KC    2304    // 9*256 im2col K

#define OUT_ELEMS   4194304
#define LOSS_OFF    4194304
#define IDX_OFF     4194305

#define GBLK  512               // gather blocks (ROWS/32)

// ---------------- device scratch ----------------
__device__ float g_ze[ROWS * EE];      // conv1 out [row][e] (bit-exact)
__device__ float g_zf[ROWS * EE];      // post-LN  [row][e] (bit-exact)
__device__ float g_znorm[ROWS];        // serial sum zf^2
__device__ float g_enorm[NE];          // serial sum e^2
__device__ float g_wp[KC * EE];        // conv1 W permuted
__device__ float g_zq[BB * EE * HW];   // straight-through zq, NCHW (fp32, exact)
__device__ int   g_idx[ROWS];
__device__ float g_lpart[GBLK];
__device__ __align__(16) __nv_bfloat16 g_zfh[ROWS * EE];   // zf in bf16
__device__ __align__(16) __nv_bfloat16 g_cbh[NE * EE];     // codebook in bf16
__device__ __align__(16) __half g_w2h[EE * KC];            // conv2 W fp16 [n][k]
__device__ __half g_v[(size_t)ROWS * NE];                  // approx v (fp16)
__device__ unsigned g_rowmin[ROWS];                        // per-row min of v

// ---------------- helpers ----------------
__device__ __forceinline__ float blk_sum(float v, float* sh) {
    int t = threadIdx.x, lane = t & 31, w = t >> 5;
    #pragma unroll
    for (int o = 16; o; o >>= 1) v += __shfl_down_sync(0xffffffffu, v, o);
    if (!lane) sh[w] = v;
    __syncthreads();
    if (w == 0) {
        float x = (lane < 8) ? sh[lane] : 0.f;
        #pragma unroll
        for (int o = 4; o; o >>= 1) x += __shfl_down_sync(0xffffffffu, x, o);
        if (!lane) sh[0] = x;
    }
    __syncthreads();
    float r = sh[0];
    __syncthreads();
    return r;
}

__device__ __forceinline__ unsigned fenc(float x) {
    unsigned u = __float_as_uint(x);
    return (u & 0x80000000u) ? ~u : (u | 0x80000000u);
}
__device__ __forceinline__ float fdec(unsigned y) {
    unsigned u = (y & 0x80000000u) ? (y ^ 0x80000000u) : ~y;
    return __uint_as_float(u);
}

// ---------------- weight permute (conv1) ----------------
__global__ __launch_bounds__(256) void permw_kernel(const float* __restrict__ Wm) {
    int i = blockIdx.x * 256 + threadIdx.x;
    if (i < KC * EE) {
        int o = i & 255;
        int kk = i >> 8;
        int ci = kk & 255;
        int khw = kk >> 8;
        g_wp[kk * 256 + o] = Wm[o * KC + ci * 9 + khw];
    }
}

// ---------------- conv2 weights -> fp16 (native [n][k] layout) ----------------
__global__ __launch_bounds__(256) void w2h_kernel(const float* __restrict__ Wm) {
    int i = blockIdx.x * 256 + threadIdx.x;
    if (i < EE * KC) g_w2h[i] = __float2half(Wm[i]);
}

// ---------------- enorm3 ----------------
#define LN_STR 260
__global__ __launch_bounds__(256) void enorm3_kernel(const float* __restrict__ cb) {
    __shared__ float ls[32 * LN_STR];
    int t = threadIdx.x;
    int r0 = blockIdx.x * 32;
    const float4* src = (const float4*)(cb + r0 * 256);
    #pragma unroll
    for (int e = 0; e < 8; e++) {
        int lin = t + (e << 8);
        float4 v = src[lin];
        int row = lin >> 6;
        int kq = (lin & 63) << 2;
        *(float4*)&ls[row * LN_STR + kq] = v;
    }
    __syncthreads();
    if (t < 32) {
        const float* x = ls + t * LN_STR;
        float s = 0.f;
        for (int k = 0; k < 256; k++)
            s = __fadd_rn(s, __fmul_rn(x[k], x[k]));
        g_enorm[r0 + t] = s;
    }
}

// ---------------- conv1: bit-exact serial-k im2col GEMM (FFMA, unchanged) ----------------
__global__ __launch_bounds__(256, 2) void conv1_exact(const float* __restrict__ X,
                                                      const float* __restrict__ bias) {
    __shared__ float As[16][132];
    __shared__ float Bs[16][132];

    int t = threadIdx.x;
    int tx = t & 15, ty = t >> 4;
    int row0 = blockIdx.x * 128;
    int n0 = blockIdx.y * 128;

    float acc[8][8];
    #pragma unroll
    for (int i = 0; i < 8; i++)
        #pragma unroll
        for (int j = 0; j < 8; j++) acc[i][j] = 0.f;

    for (int k0 = 0; k0 < KC; k0 += 16) {
        #pragma unroll
        for (int e = 0; e < 8; e++) {
            int lin = t + e * 256;
            int m = lin & 127, k = lin >> 7;
            int kk = k0 + k;
            int ci = kk & 255;
            int khw = kk >> 8;
            int kh = khw / 3, kw = khw - kh * 3;
            int row = row0 + m;
            int b = row >> 10;
            int hw = row & 1023;
            int h = (hw >> 5) + kh - 1;
            int w = (hw & 31) + kw - 1;
            float v = 0.f;
            if ((unsigned)h < 32u && (unsigned)w < 32u)
                v = X[((b * 256 + ci) << 10) + (h << 5) + w];
            As[k][m] = v;
            Bs[k][m] = g_wp[(k0 + k) * 256 + n0 + m];
        }
        __syncthreads();
        #pragma unroll
        for (int k = 0; k < 16; k++) {
            float a[8], b2[8];
            #pragma unroll
            for (int i = 0; i < 8; i++) a[i] = As[k][ty * 8 + i];
            #pragma unroll
            for (int j = 0; j < 8; j++) b2[j] = Bs[k][tx * 8 + j];
            #pragma unroll
            for (int i = 0; i < 8; i++)
                #pragma unroll
                for (int j = 0; j < 8; j++)
                    acc[i][j] = __fmaf_rn(a[i], b2[j], acc[i][j]);
        }
        __syncthreads();
    }

    #pragma unroll
    for (int i = 0; i < 8; i++) {
        int row = row0 + ty * 8 + i;
        #pragma unroll
        for (int j = 0; j < 8; j++) {
            int n = n0 + tx * 8 + j;
            g_ze[row * 256 + n] = __fadd_rn(acc[i][j], bias[n]);
        }
    }
}

// ---------------- ln3 ----------------
__global__ __launch_bounds__(256) void ln3_kernel(const float* __restrict__ g,
                                                  const float* __restrict__ be) {
    __shared__ float ls[32 * LN_STR];
    __shared__ float gg[256], bb[256];
    int t = threadIdx.x;
    int r0 = blockIdx.x * 32;
    gg[t] = g[t];
    bb[t] = be[t];
    const float4* src = (const float4*)(g_ze + r0 * 256);
    #pragma unroll
    for (int e = 0; e < 8; e++) {
        int lin = t + (e << 8);
        float4 v = src[lin];
        int row = lin >> 6;
        int kq = (lin & 63) << 2;
        *(float4*)&ls[row * LN_STR + kq] = v;
    }
    __syncthreads();
    if (t < 32) {
        float* x = ls + t * LN_STR;
        float s = 0.f;
        for (int k = 0; k < 256; k++) s = __fadd_rn(s, x[k]);
        float mu = __fmul_rn(s, 1.f / 256.f);
        float s2 = 0.f;
        for (int k = 0; k < 256; k++) {
            float tq = __fsub_rn(x[k], mu);
            s2 = __fadd_rn(s2, __fmul_rn(tq, tq));
        }
        float var = __fmul_rn(s2, 1.f / 256.f);
        float rs = __fdiv_rn(1.0f, __fsqrt_rn(__fadd_rn(var, 1e-5f)));
        float zn = 0.f;
        for (int k = 0; k < 256; k++) {
            float tq = __fsub_rn(x[k], mu);
            float a = __fmul_rn(tq, rs);
            float v = __fadd_rn(__fmul_rn(a, gg[k]), bb[k]);
            x[k] = v;
            zn = __fadd_rn(zn, __fmul_rn(v, v));
        }
        g_znorm[r0 + t] = zn;
    }
    __syncthreads();
    float4* dst = (float4*)(g_zf + r0 * 256);
    #pragma unroll
    for (int e = 0; e < 8; e++) {
        int lin = t + (e << 8);
        int row = lin >> 6;
        int kq = (lin & 63) << 2;
        dst[lin] = *(const float4*)&ls[row * LN_STR + kq];
    }
}

// ---------------- prep: zf/cb -> bf16, init rowmin ----------------
__global__ __launch_bounds__(256) void prep_bf16(const float* __restrict__ cb) {
    int i = blockIdx.x * 256 + threadIdx.x;
    const int ZQ = ROWS * EE / 4;
    if (i < ZQ) {
        float4 v = ((const float4*)g_zf)[i];
        ((__nv_bfloat162*)g_zfh)[2 * i]     = __floats2bfloat162_rn(v.x, v.y);
        ((__nv_bfloat162*)g_zfh)[2 * i + 1] = __floats2bfloat162_rn(v.z, v.w);
    } else if (i < ZQ + NE * EE / 4) {
        int j = i - ZQ;
        float4 v = ((const float4*)cb)[j];
        ((__nv_bfloat162*)g_cbh)[2 * j]     = __floats2bfloat162_rn(v.x, v.y);
        ((__nv_bfloat162*)g_cbh)[2 * j + 1] = __floats2bfloat162_rn(v.z, v.w);
    }
    if (i < ROWS) g_rowmin[i] = 0xFFFFFFFFu;
}

// ---------------- distB_wmma: bf16 tensor-core approx v + fused rowmin ----------------
#define BSP 72
__global__ __launch_bounds__(256) void distB_wmma() {
    __shared__ __nv_bfloat16 As[128 * BSP];
    __shared__ __nv_bfloat16 Bs[128 * BSP];
    __shared__ float scr[8][320];
    __shared__ unsigned sMin[128];

    int t = threadIdx.x;
    int row0 = blockIdx.x * 128;
    int nc0 = blockIdx.y * 128;
    int wid = t >> 5, lane = t & 31;
    int wm = (wid & 3) * 32;
    int wn = (wid >> 2) * 64;

    wmma::fragment<wmma::accumulator, 16, 16, 16, float> acc[2][4];
    #pragma unroll
    for (int i = 0; i < 2; i++)
        #pragma unroll
        for (int j = 0; j < 4; j++) wmma::fill_fragment(acc[i][j], 0.0f);

    for (int k0 = 0; k0 < 256; k0 += 64) {
        #pragma unroll
        for (int e = 0; e < 4; e++) {
            int lin = t + e * 256;
            int m = lin >> 3;
            int q = (lin & 7) << 3;
            *(uint4*)&As[m * BSP + q] = *(const uint4*)&g_zfh[(row0 + m) * 256 + k0 + q];
            *(uint4*)&Bs[m * BSP + q] = *(const uint4*)&g_cbh[(nc0 + m) * 256 + k0 + q];
        }
        __syncthreads();
        #pragma unroll
        for (int ks = 0; ks < 4; ks++) {
            int kk = ks * 16;
            wmma::fragment<wmma::matrix_a, 16, 16, 16, __nv_bfloat16, wmma::row_major> af[2];
            wmma::fragment<wmma::matrix_b, 16, 16, 16, __nv_bfloat16, wmma::col_major> bf[4];
            #pragma unroll
            for (int i = 0; i < 2; i++)
                wmma::load_matrix_sync(af[i], &As[(wm + 16 * i) * BSP + kk], BSP);
            #pragma unroll
            for (int j = 0; j < 4; j++)
                wmma::load_matrix_sync(bf[j], &Bs[(wn + 16 * j) * BSP + kk], BSP);
            #pragma unroll
            for (int i = 0; i < 2; i++)
                #pragma unroll
                for (int j = 0; j < 4; j++)
                    wmma::mma_sync(acc[i][j], af[i], bf[j], acc[i][j]);
        }
        __syncthreads();
    }

    if (t < 128) sMin[t] = 0xFFFFFFFFu;
    __syncthreads();

    #pragma unroll
    for (int i = 0; i < 2; i++)
        #pragma unroll
        for (int j = 0; j < 4; j++) {
            wmma::store_matrix_sync(scr[wid], acc[i][j], 20, wmma::mem_row_major);
            __syncwarp();
            #pragma unroll
            for (int e = 0; e < 8; e++) {
                int idx = lane + e * 32;
                int rr = idx >> 4, cc = idx & 15;
                int grow = row0 + wm + 16 * i + rr;
                int gcol = nc0 + wn + 16 * j + cc;
                float v = g_enorm[gcol] - 2.f * scr[wid][rr * 20 + cc];
                g_v[(size_t)grow * NE + gcol] = __float2half(v);
                atomicMin(&sMin[wm + 16 * i + rr], fenc(v));
            }
            __syncwarp();
        }
    __syncthreads();
    if (t < 128) atomicMin(&g_rowmin[row0 + t], sMin[t]);
}

// ---------------- cand2: single-pass collect + exact rescore ----------------
#define CAND_CAP 512
#define MARGIN 1.2e-3f
__global__ __launch_bounds__(256) void cand2_kernel(const float* __restrict__ cb) {
    __shared__ float zfs[4][260];
    __shared__ int   list[4][CAND_CAP];
    __shared__ int   cnt4[4];
    __shared__ unsigned long long bestkey[4];
    __shared__ float cscr[8][264];

    int t = threadIdx.x;
    int r0 = blockIdx.x * 4;
    #pragma unroll
    for (int e = 0; e < 4; e++) {
        int lin = t + e * 256;
        zfs[lin >> 8][lin & 255] = g_zf[(r0 + (lin >> 8)) * 256 + (lin & 255)];
    }
    if (t < 4) { cnt4[t] = 0; bestkey[t] = 0xFFFFFFFFFFFFFFFFull; }
    __syncthreads();

    for (int r = 0; r < 4; r++) {
        size_t rowoff = (size_t)(r0 + r) * NE;
        float thr = fdec(g_rowmin[r0 + r]) + MARGIN;
        #pragma unroll 4
        for (int i = 0; i < 32; i++) {
            int n = t + (i << 8);
            float v = __half2float(g_v[rowoff + n]);
            if (v <= thr) {
                int p = atomicAdd(&cnt4[r], 1);
                if (p < CAND_CAP) list[r][p] = n;
            }
        }
        __syncthreads();
    }

    int wid = t >> 5, lane = t & 31;
    for (int r = 0; r < 4; r++) {
        int row = r0 + r;
        int H = min(cnt4[r], CAND_CAP);
        for (int h = wid; h < H; h += 8) {
            int n = list[r][h];
            #pragma unroll
            for (int e = 0; e < 8; e++)
                cscr[wid][lane + e * 32] = cb[n * 256 + lane + e * 32];
            __syncwarp();
            if (lane == 0) {
                float dot = 0.f;
                for (int k = 0; k < 256; k++)
                    dot = __fmaf_rn(zfs[r][k], cscr[wid][k], dot);
                float S = __fadd_rn(g_znorm[row], g_enorm[n]);
                float d = __fsub_rn(S, __fmul_rn(2.0f, dot));
                unsigned long long key =
                    (((unsigned long long)__float_as_uint(d)) << 32) | (unsigned)n;
                atomicMin(&bestkey[r], key);
            }
            __syncwarp();
        }
    }
    __syncthreads();
    if (t < 4) g_idx[r0 + t] = (int)(bestkey[t] & 0xFFFFFFFFull);
}

// ---------------- gather2 ----------------
__global__ __launch_bounds__(256) void gather2_kernel(const float* __restrict__ cb) {
    __shared__ float sq[256][33];
    __shared__ int sid[32];
    __shared__ float sh[32];
    int t = threadIdx.x;
    int r0 = blockIdx.x * 32;
    if (t < 32) sid[t] = g_idx[r0 + t];
    __syncthreads();
    float local = 0.f;
    #pragma unroll 4
    for (int i = 0; i < 32; i++) {
        float e = cb[sid[i] * 256 + t];
        float z = g_ze[(r0 + i) * 256 + t];
        float d = __fsub_rn(e, z);
        sq[t][i] = __fadd_rn(z, d);
        local += d * d;
    }
    __syncthreads();
    int b = r0 >> 10, hw0 = r0 & 1023;
    int w = t >> 5, lane = t & 31;
    #pragma unroll 4
    for (int eb = 0; eb < 32; eb++) {
        int e = eb * 8 + w;
        g_zq[((b * 256 + e) << 10) + hw0 + lane] = sq[e][lane];
    }
    float s = blk_sum(local, sh);
    if (t == 0) g_lpart[blockIdx.x] = s;
}

// ---------------- conv2_wmma: fp16 tensor-core conv2 (A scaled x512) ----------------
// out error budget: fp16 product rounding -> ~4e-4 rel on out, well under 1e-3.
#define SC512 512.0f
#define INV512 (1.0f / 512.0f)
__global__ __launch_bounds__(256) void conv2_wmma(const float* __restrict__ bias,
                                                  float* __restrict__ outNCHW) {
    __shared__ __half As[128 * BSP];      // 18432 B
    __shared__ __half Bs[128 * BSP];      // 18432 B
    __shared__ float scr[8][320];         // 10240 B
    int t = threadIdx.x;
    int row0 = blockIdx.x * 128;
    int n0 = blockIdx.y * 128;
    int wid = t >> 5, lane = t & 31;
    int wm = (wid & 3) * 32;
    int wn = (wid >> 2) * 64;

    wmma::fragment<wmma::accumulator, 16, 16, 16, float> acc[2][4];
    #pragma unroll
    for (int i = 0; i < 2; i++)
        #pragma unroll
        for (int j = 0; j < 4; j++) wmma::fill_fragment(acc[i][j], 0.0f);

    for (int k0 = 0; k0 < KC; k0 += 64) {
        // A: im2col gather from fp32 g_zq, convert to fp16 scaled x512
        #pragma unroll
        for (int e = 0; e < 32; e++) {
            int lin = t + e * 256;            // 0..8191
            int m = lin & 127, k = lin >> 7;  // k in 0..63
            int kk = k0 + k;
            int ci = kk / 9;
            int r9 = kk - ci * 9;
            int kh = r9 / 3, kw = r9 - kh * 3;
            int row = row0 + m;
            int b = row >> 10;
            int hw = row & 1023;
            int h = (hw >> 5) + kh - 1;
            int w = (hw & 31) + kw - 1;
            float v = 0.f;
            if ((unsigned)h < 32u && (unsigned)w < 32u)
                v = g_zq[((b * 256 + ci) << 10) + (h << 5) + w];
            As[m * BSP + k] = __float2half(v * SC512);
        }
        // B: fp16 weights, native [n][k], vectorized
        #pragma unroll
        for (int e = 0; e < 4; e++) {
            int lin = t + e * 256;            // 0..1023
            int n = lin >> 3;
            int q = (lin & 7) << 3;
            *(uint4*)&Bs[n * BSP + q] = *(const uint4*)&g_w2h[(n0 + n) * KC + k0 + q];
        }
        __syncthreads();
        #pragma unroll
        for (int ks = 0; ks < 4; ks++) {
            int kk = ks * 16;
            wmma::fragment<wmma::matrix_a, 16, 16, 16, __half, wmma::row_major> af[2];
            wmma::fragment<wmma::matrix_b, 16, 16, 16, __half, wmma::col_major> bf[4];
            #pragma unroll
            for (int i = 0; i < 2; i++)
                wmma::load_matrix_sync(af[i], &As[(wm + 16 * i) * BSP + kk], BSP);
            #pragma unroll
            for (int j = 0; j < 4; j++)
                wmma::load_matrix_sync(bf[j], &Bs[(wn + 16 * j) * BSP + kk], BSP);
            #pragma unroll
            for (int i = 0; i < 2; i++)
                #pragma unroll
                for (int j = 0; j < 4; j++)
                    wmma::mma_sync(acc[i][j], af[i], bf[j], acc[i][j]);
        }
        __syncthreads();
    }

    // epilogue: unscale, add bias, coalesced NCHW stores
    #pragma unroll
    for (int i = 0; i < 2; i++)
        #pragma unroll
        for (int j = 0; j < 4; j++) {
            wmma::store_matrix_sync(scr[wid], acc[i][j], 20, wmma::mem_row_major);
            __syncwarp();
            #pragma unroll
            for (int e = 0; e < 8; e++) {
                int idx = lane + e * 32;
                int rr = idx & 15, cc = idx >> 4;    // rr = row (coalesced dim)
                int row = row0 + wm + 16 * i + rr;
                int n = n0 + wn + 16 * j + cc;
                int b = row >> 10;
                int hw = row & 1023;
                outNCHW[((b * 256 + n) << 10) + hw] =
                    __fmaf_rn(scr[wid][rr * 20 + cc], INV512, bias[n]);
            }
            __syncwarp();
        }
}

// ---------------- finalize ----------------
__global__ __launch_bounds__(256) void finalize_kernel(float* __restrict__ out, int out_size) {
    __shared__ float sh[32];
    int gidx = blockIdx.x * blockDim.x + threadIdx.x;
    if (gidx < ROWS && IDX_OFF + gidx < out_size)
        out[IDX_OFF + gidx] = (float)g_idx[gidx];
    if (blockIdx.x == 0) {
        float s = 0.f;
        for (int k = threadIdx.x; k < GBLK; k += 256) s += g_lpart[k];
        float tot = blk_sum(s, sh);
        if (threadIdx.x == 0 && LOSS_OFF < out_size)
            out[LOSS_OFF] = 1.25f * tot / (float)OUT_ELEMS;
    }
}

// ---------------- launcher ----------------
extern "C" void kernel_launch(void* const* d_in, const int* in_sizes, int n_in,
                              void* d_out, int out_size) {
    (void)in_sizes; (void)n_in;
    const float* z       = (const float*)d_in[0];
    const float* emb_w   = (const float*)d_in[1];
    const float* emb_b   = (const float*)d_in[2];
    const float* ln_g    = (const float*)d_in[3];
    const float* ln_b    = (const float*)d_in[4];
    const float* cb      = (const float*)d_in[5];
    const float* unemb_w = (const float*)d_in[6];
    const float* unemb_b = (const float*)d_in[7];
    float* out = (float*)d_out;

    permw_kernel<<<(KC * EE + 255) / 256, 256>>>(emb_w);
    w2h_kernel<<<(EE * KC + 255) / 256, 256>>>(unemb_w);
    enorm3_kernel<<<NE / 32, 256>>>(cb);
    conv1_exact<<<dim3(ROWS / 128, 2), 256>>>(z, emb_b);                  // -> g_ze
    ln3_kernel<<<ROWS / 32, 256>>>(ln_g, ln_b);                           // -> g_zf, g_znorm
    prep_bf16<<<(ROWS * EE + NE * EE) / 4 / 256, 256>>>(cb);              // -> g_zfh/g_cbh/rowmin
    distB_wmma<<<dim3(ROWS / 128, NE / 128), 256>>>();                    // -> g_v, g_rowmin
    cand2_kernel<<<ROWS / 4, 256>>>(cb);                                  // -> g_idx (exact)
    gather2_kernel<<<GBLK, 256>>>(cb);                                    // -> g_zq, g_lpart
    conv2_wmma<<<dim3(ROWS / 128, 2), 256>>>(unemb_b, out);               // -> out (fp16 TC)
    finalize_kernel<<<ROWS / 256, 256>>>(out, out_size);
}

// round 16
// speedup vs baseline: 2.2758x; 1.1067x over previous
#include <cuda_runtime.h>
#include <cuda_fp16.h>
#include <cuda_bf16.h>
#include <math_constants.h>
#include <mma.h>

using namespace nvcuda;

// Problem constants
#define BB    16
#define CC    256
#define HH    32
#define WW    32
#define EE    256
#define NE    8192
#define HW    1024
#define ROWS  16384   // B*H*W
#define KC    2304    // 9*256 im2col K

#define OUT_ELEMS   4194304
#define LOSS_OFF    4194304
#define IDX_OFF     4194305

#define GBLK  512               // gather blocks (ROWS/32)

// ---------------- device scratch ----------------
__device__ float g_ze[ROWS * EE];      // conv1 out [row][e] (bit-exact)
__device__ float g_zf[ROWS * EE];      // post-LN  [row][e] (bit-exact)
__device__ float g_znorm[ROWS];        // serial sum zf^2
__device__ float g_enorm[NE];          // serial sum e^2
__device__ float g_wp[KC * EE];        // conv1 W permuted [(khw*256+ci)][o]
__device__ int   g_idx[ROWS];
__device__ float g_lpart[GBLK];
__device__ __align__(16) __nv_bfloat16 g_zfh[ROWS * EE];   // zf in bf16
__device__ __align__(16) __nv_bfloat16 g_cbh[NE * EE];     // codebook in bf16
__device__ __align__(16) __half g_w2h[EE * KC];            // conv2 W fp16 [n][kk'=(khw*256+ci)]
__device__ __align__(16) __half g_zqh[BB * EE * HW];       // zq fp16 x512, NCHW
__device__ __half g_v[(size_t)ROWS * NE];                  // approx v (fp16)
__device__ unsigned g_rowmin[ROWS];                        // per-row min of v

// ---------------- helpers ----------------
__device__ __forceinline__ float blk_sum(float v, float* sh) {
    int t = threadIdx.x, lane = t & 31, w = t >> 5;
    #pragma unroll
    for (int o = 16; o; o >>= 1) v += __shfl_down_sync(0xffffffffu, v, o);
    if (!lane) sh[w] = v;
    __syncthreads();
    if (w == 0) {
        float x = (lane < 8) ? sh[lane] : 0.f;
        #pragma unroll
        for (int o = 4; o; o >>= 1) x += __shfl_down_sync(0xffffffffu, x, o);
        if (!lane) sh[0] = x;
    }
    __syncthreads();
    float r = sh[0];
    __syncthreads();
    return r;
}

__device__ __forceinline__ unsigned fenc(float x) {
    unsigned u = __float_as_uint(x);
    return (u & 0x80000000u) ? ~u : (u | 0x80000000u);
}
__device__ __forceinline__ float fdec(unsigned y) {
    unsigned u = (y & 0x80000000u) ? (y ^ 0x80000000u) : ~y;
    return __uint_as_float(u);
}

// ---------------- conv1 weight permute ----------------
__global__ __launch_bounds__(256) void permw_kernel(const float* __restrict__ Wm) {
    int i = blockIdx.x * 256 + threadIdx.x;
    if (i < KC * EE) {
        int o = i & 255;
        int kk = i >> 8;
        int ci = kk & 255;
        int khw = kk >> 8;
        g_wp[kk * 256 + o] = Wm[o * KC + ci * 9 + khw];
    }
}

// ---------------- conv2 weight permute -> fp16 [n][kk'] + rowmin init ----------------
__global__ __launch_bounds__(256) void permw2h_kernel(const float* __restrict__ Wm) {
    int n = blockIdx.x;                // 256 blocks
    int t = threadIdx.x;
    int gid = n * 256 + t;
    if (gid < ROWS) g_rowmin[gid] = 0xFFFFFFFFu;
    for (int kk = t; kk < KC; kk += 256) {
        int ci = kk & 255;
        int khw = kk >> 8;
        g_w2h[n * KC + kk] = __float2half(Wm[n * KC + ci * 9 + khw]);
    }
}

// ---------------- enorm3 + codebook->bf16 ----------------
#define LN_STR 260
__global__ __launch_bounds__(256) void enorm3_kernel(const float* __restrict__ cb) {
    __shared__ float ls[32 * LN_STR];
    int t = threadIdx.x;
    int r0 = blockIdx.x * 32;
    const float4* src = (const float4*)(cb + r0 * 256);
    __nv_bfloat162* hc = (__nv_bfloat162*)(g_cbh + r0 * 256);
    #pragma unroll
    for (int e = 0; e < 8; e++) {
        int lin = t + (e << 8);
        float4 v = src[lin];
        hc[2 * lin]     = __floats2bfloat162_rn(v.x, v.y);
        hc[2 * lin + 1] = __floats2bfloat162_rn(v.z, v.w);
        int row = lin >> 6;
        int kq = (lin & 63) << 2;
        *(float4*)&ls[row * LN_STR + kq] = v;
    }
    __syncthreads();
    if (t < 32) {
        const float* x = ls + t * LN_STR;
        float s = 0.f;
        for (int k = 0; k < 256; k++)
            s = __fadd_rn(s, __fmul_rn(x[k], x[k]));
        g_enorm[r0 + t] = s;
    }
}

// ---------------- conv1: bit-exact serial-k im2col GEMM (unchanged) ----------------
__global__ __launch_bounds__(256, 2) void conv1_exact(const float* __restrict__ X,
                                                      const float* __restrict__ bias) {
    __shared__ float As[16][132];
    __shared__ float Bs[16][132];

    int t = threadIdx.x;
    int tx = t & 15, ty = t >> 4;
    int row0 = blockIdx.x * 128;
    int n0 = blockIdx.y * 128;

    float acc[8][8];
    #pragma unroll
    for (int i = 0; i < 8; i++)
        #pragma unroll
        for (int j = 0; j < 8; j++) acc[i][j] = 0.f;

    for (int k0 = 0; k0 < KC; k0 += 16) {
        #pragma unroll
        for (int e = 0; e < 8; e++) {
            int lin = t + e * 256;
            int m = lin & 127, k = lin >> 7;
            int kk = k0 + k;
            int ci = kk & 255;
            int khw = kk >> 8;
            int kh = khw / 3, kw = khw - kh * 3;
            int row = row0 + m;
            int b = row >> 10;
            int hw = row & 1023;
            int h = (hw >> 5) + kh - 1;
            int w = (hw & 31) + kw - 1;
            float v = 0.f;
            if ((unsigned)h < 32u && (unsigned)w < 32u)
                v = X[((b * 256 + ci) << 10) + (h << 5) + w];
            As[k][m] = v;
            Bs[k][m] = g_wp[(k0 + k) * 256 + n0 + m];
        }
        __syncthreads();
        #pragma unroll
        for (int k = 0; k < 16; k++) {
            float a[8], b2[8];
            #pragma unroll
            for (int i = 0; i < 8; i++) a[i] = As[k][ty * 8 + i];
            #pragma unroll
            for (int j = 0; j < 8; j++) b2[j] = Bs[k][tx * 8 + j];
            #pragma unroll
            for (int i = 0; i < 8; i++)
                #pragma unroll
                for (int j = 0; j < 8; j++)
                    acc[i][j] = __fmaf_rn(a[i], b2[j], acc[i][j]);
        }
        __syncthreads();
    }

    #pragma unroll
    for (int i = 0; i < 8; i++) {
        int row = row0 + ty * 8 + i;
        #pragma unroll
        for (int j = 0; j < 8; j++) {
            int n = n0 + tx * 8 + j;
            g_ze[row * 256 + n] = __fadd_rn(acc[i][j], bias[n]);
        }
    }
}

// ---------------- ln3 + zf->bf16 ----------------
__global__ __launch_bounds__(256) void ln3_kernel(const float* __restrict__ g,
                                                  const float* __restrict__ be) {
    __shared__ float ls[32 * LN_STR];
    __shared__ float gg[256], bb[256];
    int t = threadIdx.x;
    int r0 = blockIdx.x * 32;
    gg[t] = g[t];
    bb[t] = be[t];
    const float4* src = (const float4*)(g_ze + r0 * 256);
    #pragma unroll
    for (int e = 0; e < 8; e++) {
        int lin = t + (e << 8);
        float4 v = src[lin];
        int row = lin >> 6;
        int kq = (lin & 63) << 2;
        *(float4*)&ls[row * LN_STR + kq] = v;
    }
    __syncthreads();
    if (t < 32) {
        float* x = ls + t * LN_STR;
        float s = 0.f;
        for (int k = 0; k < 256; k++) s = __fadd_rn(s, x[k]);
        float mu = __fmul_rn(s, 1.f / 256.f);
        float s2 = 0.f;
        for (int k = 0; k < 256; k++) {
            float tq = __fsub_rn(x[k], mu);
            s2 = __fadd_rn(s2, __fmul_rn(tq, tq));
        }
        float var = __fmul_rn(s2, 1.f / 256.f);
        float rs = __fdiv_rn(1.0f, __fsqrt_rn(__fadd_rn(var, 1e-5f)));
        float zn = 0.f;
        for (int k = 0; k < 256; k++) {
            float tq = __fsub_rn(x[k], mu);
            float a = __fmul_rn(tq, rs);
            float v = __fadd_rn(__fmul_rn(a, gg[k]), bb[k]);
            x[k] = v;
            zn = __fadd_rn(zn, __fmul_rn(v, v));
        }
        g_znorm[r0 + t] = zn;
    }
    __syncthreads();
    float4* dst = (float4*)(g_zf + r0 * 256);
    __nv_bfloat162* hz = (__nv_bfloat162*)(g_zfh + r0 * 256);
    #pragma unroll
    for (int e = 0; e < 8; e++) {
        int lin = t + (e << 8);
        int row = lin >> 6;
        int kq = (lin & 63) << 2;
        float4 v = *(const float4*)&ls[row * LN_STR + kq];
        dst[lin] = v;
        hz[2 * lin]     = __floats2bfloat162_rn(v.x, v.y);
        hz[2 * lin + 1] = __floats2bfloat162_rn(v.z, v.w);
    }
}

// ---------------- distB_wmma: bf16 TC approx v + fused rowmin ----------------
#define BSP 72
__global__ __launch_bounds__(256) void distB_wmma() {
    __shared__ __nv_bfloat16 As[128 * BSP];
    __shared__ __nv_bfloat16 Bs[128 * BSP];
    __shared__ float scr[8][320];
    __shared__ unsigned sMin[128];
    __shared__ float enormS[128];

    int t = threadIdx.x;
    int row0 = blockIdx.x * 128;
    int nc0 = blockIdx.y * 128;
    int wid = t >> 5, lane = t & 31;
    int wm = (wid & 3) * 32;
    int wn = (wid >> 2) * 64;

    if (t < 128) { sMin[t] = 0xFFFFFFFFu; enormS[t] = g_enorm[nc0 + t]; }

    wmma::fragment<wmma::accumulator, 16, 16, 16, float> acc[2][4];
    #pragma unroll
    for (int i = 0; i < 2; i++)
        #pragma unroll
        for (int j = 0; j < 4; j++) wmma::fill_fragment(acc[i][j], 0.0f);

    for (int k0 = 0; k0 < 256; k0 += 64) {
        #pragma unroll
        for (int e = 0; e < 4; e++) {
            int lin = t + e * 256;
            int m = lin >> 3;
            int q = (lin & 7) << 3;
            *(uint4*)&As[m * BSP + q] = *(const uint4*)&g_zfh[(row0 + m) * 256 + k0 + q];
            *(uint4*)&Bs[m * BSP + q] = *(const uint4*)&g_cbh[(nc0 + m) * 256 + k0 + q];
        }
        __syncthreads();
        #pragma unroll
        for (int ks = 0; ks < 4; ks++) {
            int kk = ks * 16;
            wmma::fragment<wmma::matrix_a, 16, 16, 16, __nv_bfloat16, wmma::row_major> af[2];
            wmma::fragment<wmma::matrix_b, 16, 16, 16, __nv_bfloat16, wmma::col_major> bf[4];
            #pragma unroll
            for (int i = 0; i < 2; i++)
                wmma::load_matrix_sync(af[i], &As[(wm + 16 * i) * BSP + kk], BSP);
            #pragma unroll
            for (int j = 0; j < 4; j++)
                wmma::load_matrix_sync(bf[j], &Bs[(wn + 16 * j) * BSP + kk], BSP);
            #pragma unroll
            for (int i = 0; i < 2; i++)
                #pragma unroll
                for (int j = 0; j < 4; j++)
                    wmma::mma_sync(acc[i][j], af[i], bf[j], acc[i][j]);
        }
        __syncthreads();
    }

    #pragma unroll
    for (int i = 0; i < 2; i++)
        #pragma unroll
        for (int j = 0; j < 4; j++) {
            wmma::store_matrix_sync(scr[wid], acc[i][j], 20, wmma::mem_row_major);
            __syncwarp();
            #pragma unroll
            for (int e = 0; e < 4; e++) {
                int idx = lane + e * 32;          // 0..127
                int rr = idx >> 3, ccp = idx & 7;
                int lrow = wm + 16 * i + rr;
                int lcol = wn + 16 * j + ccp * 2;
                float v0 = enormS[lcol]     - 2.f * scr[wid][rr * 20 + ccp * 2];
                float v1 = enormS[lcol + 1] - 2.f * scr[wid][rr * 20 + ccp * 2 + 1];
                *(__half2*)&g_v[(size_t)(row0 + lrow) * NE + nc0 + lcol] =
                    __floats2half2_rn(v0, v1);
                float mv = fminf(v0, v1);
                mv = fminf(mv, __shfl_down_sync(0xffffffffu, mv, 4));
                mv = fminf(mv, __shfl_down_sync(0xffffffffu, mv, 2));
                mv = fminf(mv, __shfl_down_sync(0xffffffffu, mv, 1));
                if ((lane & 7) == 0) atomicMin(&sMin[lrow], fenc(mv));
            }
            __syncwarp();
        }
    __syncthreads();
    if (t < 128) atomicMin(&g_rowmin[row0 + t], sMin[t]);
}

// ---------------- cand2: single-pass collect + exact rescore ----------------
#define CAND_CAP 512
#define MARGIN 1.2e-3f
__global__ __launch_bounds__(256) void cand2_kernel(const float* __restrict__ cb) {
    __shared__ float zfs[4][260];
    __shared__ int   list[4][CAND_CAP];
    __shared__ int   cnt4[4];
    __shared__ unsigned long long bestkey[4];
    __shared__ float cscr[8][264];

    int t = threadIdx.x;
    int r0 = blockIdx.x * 4;
    #pragma unroll
    for (int e = 0; e < 4; e++) {
        int lin = t + e * 256;
        zfs[lin >> 8][lin & 255] = g_zf[(r0 + (lin >> 8)) * 256 + (lin & 255)];
    }
    if (t < 4) { cnt4[t] = 0; bestkey[t] = 0xFFFFFFFFFFFFFFFFull; }
    __syncthreads();

    for (int r = 0; r < 4; r++) {
        size_t rowoff = (size_t)(r0 + r) * NE;
        float thr = fdec(g_rowmin[r0 + r]) + MARGIN;
        #pragma unroll 4
        for (int i = 0; i < 32; i++) {
            int n = t + (i << 8);
            float v = __half2float(g_v[rowoff + n]);
            if (v <= thr) {
                int p = atomicAdd(&cnt4[r], 1);
                if (p < CAND_CAP) list[r][p] = n;
            }
        }
        __syncthreads();
    }

    int wid = t >> 5, lane = t & 31;
    for (int r = 0; r < 4; r++) {
        int row = r0 + r;
        int H = min(cnt4[r], CAND_CAP);
        for (int h = wid; h < H; h += 8) {
            int n = list[r][h];
            #pragma unroll
            for (int e = 0; e < 8; e++)
                cscr[wid][lane + e * 32] = cb[n * 256 + lane + e * 32];
            __syncwarp();
            if (lane == 0) {
                float dot = 0.f;
                for (int k = 0; k < 256; k++)
                    dot = __fmaf_rn(zfs[r][k], cscr[wid][k], dot);
                float S = __fadd_rn(g_znorm[row], g_enorm[n]);
                float d = __fsub_rn(S, __fmul_rn(2.0f, dot));
                unsigned long long key =
                    (((unsigned long long)__float_as_uint(d)) << 32) | (unsigned)n;
                atomicMin(&bestkey[r], key);
            }
            __syncwarp();
        }
    }
    __syncthreads();
    if (t < 4) g_idx[r0 + t] = (int)(bestkey[t] & 0xFFFFFFFFull);
}

// ---------------- gather2: straight-through -> fp16 x512 NCHW + loss partials ----------------
#define SC512 512.0f
#define INV512 (1.0f / 512.0f)
__global__ __launch_bounds__(256) void gather2_kernel(const float* __restrict__ cb) {
    __shared__ float sq[256][33];
    __shared__ int sid[32];
    __shared__ float sh[32];
    int t = threadIdx.x;
    int r0 = blockIdx.x * 32;
    if (t < 32) sid[t] = g_idx[r0 + t];
    __syncthreads();
    float local = 0.f;
    #pragma unroll 4
    for (int i = 0; i < 32; i++) {
        float e = cb[sid[i] * 256 + t];
        float z = g_ze[(r0 + i) * 256 + t];
        float d = __fsub_rn(e, z);
        sq[t][i] = __fadd_rn(z, d);              // straight-through bits (fp32)
        local += d * d;
    }
    __syncthreads();
    int b = r0 >> 10, hw0 = r0 & 1023;
    int w = t >> 5, lane = t & 31;
    #pragma unroll 4
    for (int eb = 0; eb < 32; eb++) {
        int e = eb * 8 + w;
        g_zqh[((b * 256 + e) << 10) + hw0 + lane] = __float2half(sq[e][lane] * SC512);
    }
    float s = blk_sum(local, sh);
    if (t == 0) g_lpart[blockIdx.x] = s;
}

// ---------------- conv2_wmma: fp16 TC conv2 (A pre-scaled x512, k-order khw-major) ----------------
__global__ __launch_bounds__(256) void conv2_wmma(const float* __restrict__ bias,
                                                  float* __restrict__ outNCHW) {
    __shared__ __half As[128 * BSP];
    __shared__ __half Bs[128 * BSP];
    __shared__ float scr[8][320];
    int t = threadIdx.x;
    int row0 = blockIdx.x * 128;
    int n0 = blockIdx.y * 128;
    int wid = t >> 5, lane = t & 31;
    int wm = (wid & 3) * 32;
    int wn = (wid >> 2) * 64;

    wmma::fragment<wmma::accumulator, 16, 16, 16, float> acc[2][4];
    #pragma unroll
    for (int i = 0; i < 2; i++)
        #pragma unroll
        for (int j = 0; j < 4; j++) wmma::fill_fragment(acc[i][j], 0.0f);

    const __half hzero = __float2half(0.f);
    for (int k0 = 0; k0 < KC; k0 += 64) {
        // A: im2col gather of fp16 zqh (cheap kk decomposition: kk' = khw*256+ci)
        #pragma unroll
        for (int e = 0; e < 32; e++) {
            int lin = t + e * 256;            // 0..8191
            int m = lin & 127, k = lin >> 7;  // k 0..63
            int kk = k0 + k;
            int ci = kk & 255;
            int khw = kk >> 8;
            int kh = khw / 3, kw = khw - kh * 3;
            int row = row0 + m;
            int b = row >> 10;
            int hw = row & 1023;
            int h = (hw >> 5) + kh - 1;
            int w = (hw & 31) + kw - 1;
            __half v = hzero;
            if ((unsigned)h < 32u && (unsigned)w < 32u)
                v = g_zqh[((b * 256 + ci) << 10) + (h << 5) + w];
            As[m * BSP + k] = v;
        }
        // B: fp16 permuted weights [n][kk'], vectorized
        #pragma unroll
        for (int e = 0; e < 4; e++) {
            int lin = t + e * 256;
            int n = lin >> 3;
            int q = (lin & 7) << 3;
            *(uint4*)&Bs[n * BSP + q] = *(const uint4*)&g_w2h[(n0 + n) * KC + k0 + q];
        }
        __syncthreads();
        #pragma unroll
        for (int ks = 0; ks < 4; ks++) {
            int kk = ks * 16;
            wmma::fragment<wmma::matrix_a, 16, 16, 16, __half, wmma::row_major> af[2];
            wmma::fragment<wmma::matrix_b, 16, 16, 16, __half, wmma::col_major> bf[4];
            #pragma unroll
            for (int i = 0; i < 2; i++)
                wmma::load_matrix_sync(af[i], &As[(wm + 16 * i) * BSP + kk], BSP);
            #pragma unroll
            for (int j = 0; j < 4; j++)
                wmma::load_matrix_sync(bf[j], &Bs[(wn + 16 * j) * BSP + kk], BSP);
            #pragma unroll
            for (int i = 0; i < 2; i++)
                #pragma unroll
                for (int j = 0; j < 4; j++)
                    wmma::mma_sync(acc[i][j], af[i], bf[j], acc[i][j]);
        }
        __syncthreads();
    }

    #pragma unroll
    for (int i = 0; i < 2; i++)
        #pragma unroll
        for (int j = 0; j < 4; j++) {
            wmma::store_matrix_sync(scr[wid], acc[i][j], 20, wmma::mem_row_major);
            __syncwarp();
            #pragma unroll
            for (int e = 0; e < 8; e++) {
                int idx = lane + e * 32;
                int rr = idx & 15, cc = idx >> 4;
                int row = row0 + wm + 16 * i + rr;
                int n = n0 + wn + 16 * j + cc;
                int b = row >> 10;
                int hw = row & 1023;
                outNCHW[((b * 256 + n) << 10) + hw] =
                    __fmaf_rn(scr[wid][rr * 20 + cc], INV512, bias[n]);
            }
            __syncwarp();
        }
}

// ---------------- finalize ----------------
__global__ __launch_bounds__(256) void finalize_kernel(float* __restrict__ out, int out_size) {
    __shared__ float sh[32];
    int gidx = blockIdx.x * blockDim.x + threadIdx.x;
    if (gidx < ROWS && IDX_OFF + gidx < out_size)
        out[IDX_OFF + gidx] = (float)g_idx[gidx];
    if (blockIdx.x == 0) {
        float s = 0.f;
        for (int k = threadIdx.x; k < GBLK; k += 256) s += g_lpart[k];
        float tot = blk_sum(s, sh);
        if (threadIdx.x == 0 && LOSS_OFF < out_size)
            out[LOSS_OFF] = 1.25f * tot / (float)OUT_ELEMS;
    }
}

// ---------------- launcher ----------------
extern "C" void kernel_launch(void* const* d_in, const int* in_sizes, int n_in,
                              void* d_out, int out_size) {
    (void)in_sizes; (void)n_in;
    const float* z       = (const float*)d_in[0];
    const float* emb_w   = (const float*)d_in[1];
    const float* emb_b   = (const float*)d_in[2];
    const float* ln_g    = (const float*)d_in[3];
    const float* ln_b    = (const float*)d_in[4];
    const float* cb      = (const float*)d_in[5];
    const float* unemb_w = (const float*)d_in[6];
    const float* unemb_b = (const float*)d_in[7];
    float* out = (float*)d_out;

    permw_kernel<<<(KC * EE + 255) / 256, 256>>>(emb_w);
    permw2h_kernel<<<EE, 256>>>(unemb_w);                                 // W2 fp16 + rowmin init
    enorm3_kernel<<<NE / 32, 256>>>(cb);                                  // enorm + cbh
    conv1_exact<<<dim3(ROWS / 128, 2), 256>>>(z, emb_b);                  // -> g_ze
    ln3_kernel<<<ROWS / 32, 256>>>(ln_g, ln_b);                           // -> g_zf/zfh/znorm
    distB_wmma<<<dim3(ROWS / 128, NE / 128), 256>>>();                    // -> g_v, g_rowmin
    cand2_kernel<<<ROWS / 4, 256>>>(cb);                                  // -> g_idx (exact)
    gather2_kernel<<<GBLK, 256>>>(cb);                                    // -> g_zqh, g_lpart
    conv2_wmma<<<dim3(ROWS / 128, 2), 256>>>(unemb_b, out);               // -> out (fp16 TC)
    finalize_kernel<<<ROWS / 256, 256>>>(out, out_size);
}